// round 5
// baseline (speedup 1.0000x reference)
#include <cuda_runtime.h>
#include <cstdint>

#define EMBED 2048
#define NHEAD 16
#define HDIM  128
#define BATCH 2
#define SEQ   2048
#define MROWS (BATCH*SEQ)   // 4096

// Scratch (allocation-free contract: __device__ globals)
__device__ float g_Q[(size_t)BATCH*NHEAD*SEQ*HDIM];
__device__ float g_K[(size_t)BATCH*NHEAD*SEQ*HDIM];
__device__ float g_V[(size_t)BATCH*NHEAD*SEQ*HDIM];
__device__ float g_C[(size_t)MROWS*EMBED];
__device__ float g_xr[(size_t)MROWS*EMBED];
__device__ float g_Wr[(size_t)4*EMBED*EMBED];

__device__ __forceinline__ float to_tf32(float x) {
    uint32_t u;
    asm("cvt.rna.tf32.f32 %0, %1;" : "=r"(u) : "f"(x));
    return __uint_as_float(u);
}

__device__ __forceinline__ uint32_t smem_u32(const void* p) {
    uint32_t a;
    asm("{ .reg .u64 t; cvta.to.shared.u64 t, %1; cvt.u32.u64 %0, t; }" : "=r"(a) : "l"(p));
    return a;
}

#define CP_ASYNC16(dst, src) \
    asm volatile("cp.async.cg.shared.global [%0], [%1], 16;" :: "r"(dst), "l"(src))
#define CP_COMMIT()  asm volatile("cp.async.commit_group;" ::: "memory")
#define CP_WAIT0()   asm volatile("cp.async.wait_group 0;" ::: "memory")
#define CP_WAIT1()   asm volatile("cp.async.wait_group 1;" ::: "memory")

__device__ __forceinline__ void mma_tf32(float c[4], const float a[4], float b0, float b1) {
    asm("mma.sync.aligned.m16n8k8.row.col.f32.tf32.tf32.f32 "
        "{%0,%1,%2,%3}, {%4,%5,%6,%7}, {%8,%9}, {%0,%1,%2,%3};"
        : "+f"(c[0]), "+f"(c[1]), "+f"(c[2]), "+f"(c[3])
        : "r"(__float_as_uint(a[0])), "r"(__float_as_uint(a[1])),
          "r"(__float_as_uint(a[2])), "r"(__float_as_uint(a[3])),
          "r"(__float_as_uint(b0)),  "r"(__float_as_uint(b1)));
}

// ===================== tf32 rounding pre-pass =====================
__global__ void round_tf32_kernel(const float* __restrict__ src,
                                  float* __restrict__ dst, int n4) {
    int i = blockIdx.x * blockDim.x + threadIdx.x;
    if (i < n4) {
        float4 v = ((const float4*)src)[i];
        v.x = to_tf32(v.x); v.y = to_tf32(v.y);
        v.z = to_tf32(v.z); v.w = to_tf32(v.w);
        ((float4*)dst)[i] = v;
    }
}

// ---------------------------------------------------------------------------
// TF32 GEMM v2: C[M,N] = A[M,K] @ W[N,K]^T + bias.  A, W pre-rounded to tf32.
// Block 128x128, K-tile 32, 8 warps. Double-buffered cp.async loads.
// mode 0: C row-major fp32. mode 1: scatter to [B,H,S,D], tf32-rounded.
// ---------------------------------------------------------------------------
#define GSTG (2*128*36)              // floats per stage (As+Bs)
#define GEMM_SMEM (2*GSTG*4)         // 73,728 B

__global__ void __launch_bounds__(256, 2) gemm_tf32_kernel(
    const float* __restrict__ A, const float* __restrict__ W,
    const float* __restrict__ bias, float* __restrict__ C, int mode)
{
    const int N = EMBED, K = EMBED;
    extern __shared__ float sm[];

    int tid  = threadIdx.x;
    int lane = tid & 31, wid = tid >> 5;
    int tig  = lane & 3, grp = lane >> 2;
    int wm   = (wid >> 2) * 64;
    int wn   = (wid & 3) * 32;
    int bm   = blockIdx.y * 128, bn = blockIdx.x * 128;

    // cp.async geometry: thread t copies 4 A-chunks + 4 B-chunks of 16B.
    // row = t>>1, chunk cols cc = (t&1)*4 .. +3 of 8 per row (32 floats).
    int lrow = tid >> 1;
    int cc0  = (tid & 1) * 4;
    uint32_t smbase = smem_u32(sm);
    const char* srcA = (const char*)(A + (size_t)(bm + lrow) * K) + cc0 * 16;
    const char* srcB = (const char*)(W + (size_t)(bn + lrow) * K) + cc0 * 16;
    uint32_t dA = smbase + lrow * 144 + cc0 * 16;            // [r][36] rows = 144B
    uint32_t dB = dA + 4608 * 4;                             // Bs after As

    float acc[4][4][4];
#pragma unroll
    for (int i = 0; i < 4; i++)
#pragma unroll
        for (int j = 0; j < 4; j++)
#pragma unroll
            for (int r = 0; r < 4; r++) acc[i][j][r] = 0.f;

    // prologue: load tile 0 into buf 0
#pragma unroll
    for (int p = 0; p < 4; p++) CP_ASYNC16(dA + p * 16, srcA + p * 16);
#pragma unroll
    for (int p = 0; p < 4; p++) CP_ASYNC16(dB + p * 16, srcB + p * 16);
    CP_COMMIT();

    for (int kt = 0; kt < 64; kt++) {
        int c = kt & 1;
        if (kt < 63) {
            uint32_t bufoff = (1 - c) * (GSTG * 4);
            const char* ga = srcA + (size_t)(kt + 1) * 128;
            const char* gb = srcB + (size_t)(kt + 1) * 128;
#pragma unroll
            for (int p = 0; p < 4; p++) CP_ASYNC16(dA + bufoff + p * 16, ga + p * 16);
#pragma unroll
            for (int p = 0; p < 4; p++) CP_ASYNC16(dB + bufoff + p * 16, gb + p * 16);
            CP_COMMIT();
            CP_WAIT1();
        } else {
            CP_WAIT0();
        }
        __syncthreads();

        const float* As = sm + c * GSTG;
        const float* Bs = As + 4608;
#pragma unroll
        for (int ks = 0; ks < 4; ks++) {
            int k0 = ks * 8;
            float a[4][4], bb[4][2];
#pragma unroll
            for (int mi = 0; mi < 4; mi++) {
                int m0 = wm + mi * 16;
                a[mi][0] = As[(m0 + grp    )*36 + k0 + tig    ];
                a[mi][1] = As[(m0 + grp + 8)*36 + k0 + tig    ];
                a[mi][2] = As[(m0 + grp    )*36 + k0 + tig + 4];
                a[mi][3] = As[(m0 + grp + 8)*36 + k0 + tig + 4];
            }
#pragma unroll
            for (int ni = 0; ni < 4; ni++) {
                int n0 = wn + ni * 8;
                bb[ni][0] = Bs[(n0 + grp)*36 + k0 + tig    ];
                bb[ni][1] = Bs[(n0 + grp)*36 + k0 + tig + 4];
            }
#pragma unroll
            for (int mi = 0; mi < 4; mi++)
#pragma unroll
                for (int ni = 0; ni < 4; ni++)
                    mma_tf32(acc[mi][ni], a[mi], bb[ni][0], bb[ni][1]);
        }
        __syncthreads();
    }

#pragma unroll
    for (int mi = 0; mi < 4; mi++) {
#pragma unroll
        for (int ni = 0; ni < 4; ni++) {
            int m0 = bm + wm + mi * 16 + grp;
            int n0 = bn + wn + ni * 8 + tig * 2;
            float bv0 = bias[n0], bv1 = bias[n0 + 1];
            float v00 = acc[mi][ni][0] + bv0, v01 = acc[mi][ni][1] + bv1;
            float v10 = acc[mi][ni][2] + bv0, v11 = acc[mi][ni][3] + bv1;
            if (mode == 0) {
                C[(size_t)m0 * N + n0]       = v00;
                C[(size_t)m0 * N + n0 + 1]   = v01;
                C[(size_t)(m0+8) * N + n0]   = v10;
                C[(size_t)(m0+8) * N + n0+1] = v11;
            } else {
                // tf32-rounded so the attention can cp.async raw bytes
                size_t i0 = ((size_t)((m0 >> 11) * NHEAD + (n0 >> 7))) * (SEQ * HDIM)
                          + (size_t)(m0 & (SEQ-1)) * HDIM + (n0 & (HDIM-1));
                size_t i1 = ((size_t)(((m0+8) >> 11) * NHEAD + (n0 >> 7))) * (SEQ * HDIM)
                          + (size_t)((m0+8) & (SEQ-1)) * HDIM + (n0 & (HDIM-1));
                C[i0] = to_tf32(v00); C[i0 + 1] = to_tf32(v01);
                C[i1] = to_tf32(v10); C[i1 + 1] = to_tf32(v11);
            }
        }
    }
}

// ---------------------------------------------------------------------------
// Causal flash attention v3.
// R4 math/fragments (proven), loads replaced by cp.async pipeline:
//   K double-buffered (loads K(t+1) during mma(t));
//   V single-buffered (V(t+1) issued after PV(t), lands during QK(t+1)).
// Inputs Q/K/V already tf32. Scale applied to S post-mma (1 fmul, exact).
// smem = 2*K(64x132) + V(64x136) = 102,400 B -> 2 CTAs/SM.
// ---------------------------------------------------------------------------
#define SQK 132
#define SV  136
#define KTILE_ELEMS (64*SQK)
#define ATTN_SMEM ((2*KTILE_ELEMS + 64*SV) * 4)

__global__ void __launch_bounds__(128, 2) attn_kernel(
    const float* __restrict__ Q, const float* __restrict__ K,
    const float* __restrict__ V, float* __restrict__ Ctx)
{
    extern __shared__ float sm[];
    float* kb[2] = { sm, sm + KTILE_ELEMS };
    float* Vs    = sm + 2 * KTILE_ELEMS;

    int tid  = threadIdx.x;
    int lane = tid & 31, wid = tid >> 5;          // 4 warps
    int tig  = lane & 3, grp = lane >> 2;
    int bh   = blockIdx.y;
    int qt   = gridDim.x - 1 - blockIdx.x;        // big-work blocks first
    int q0   = qt * 64;
    int wrow = wid * 16;

    const size_t off = (size_t)bh * SEQ * HDIM;
    const float* Qp = Q + off + (size_t)q0 * HDIM;
    const float* Kp = K + off;
    const float* Vp = V + off;
    const float scale = 0.08838834764831845f;     // 1/sqrt(128)

    // cp.async geometry: thread t copies 16 chunks of 16B: row = t>>1,
    // chunks cc0..cc0+15 of 32 per 512B row.
    int lrow = tid >> 1;
    int cc0  = (tid & 1) * 16;
    uint32_t kdst[2], vdst;
    kdst[0] = smem_u32(kb[0]) + lrow * (SQK*4) + cc0 * 16;
    kdst[1] = smem_u32(kb[1]) + lrow * (SQK*4) + cc0 * 16;
    vdst    = smem_u32(Vs)    + lrow * (SV*4)  + cc0 * 16;

    // ---- stage Q through kb[0], build register fragments ----
    {
        const char* gq = (const char*)(Qp + (size_t)lrow * HDIM) + cc0 * 16;
#pragma unroll
        for (int p = 0; p < 16; p++) CP_ASYNC16(kdst[0] + p * 16, gq + p * 16);
        CP_COMMIT(); CP_WAIT0();
        __syncthreads();
    }
    float qf[16][4];
#pragma unroll
    for (int ks = 0; ks < 16; ks++) {
        int k0 = ks * 8;
        qf[ks][0] = kb[0][(wrow + grp    )*SQK + k0 + tig    ];
        qf[ks][1] = kb[0][(wrow + grp + 8)*SQK + k0 + tig    ];
        qf[ks][2] = kb[0][(wrow + grp    )*SQK + k0 + tig + 4];
        qf[ks][3] = kb[0][(wrow + grp + 8)*SQK + k0 + tig + 4];
    }
    __syncthreads();   // everyone done reading Q from kb[0]

    // ---- prologue: K(0) -> kb[0], V(0) -> Vs ----
    {
        const char* gk = (const char*)(Kp + (size_t)lrow * HDIM) + cc0 * 16;
        const char* gv = (const char*)(Vp + (size_t)lrow * HDIM) + cc0 * 16;
#pragma unroll
        for (int p = 0; p < 16; p++) CP_ASYNC16(kdst[0] + p * 16, gk + p * 16);
        CP_COMMIT();
#pragma unroll
        for (int p = 0; p < 16; p++) CP_ASYNC16(vdst + p * 16, gv + p * 16);
        CP_COMMIT();
    }

    float o[16][4];
#pragma unroll
    for (int i = 0; i < 16; i++)
#pragma unroll
        for (int r = 0; r < 4; r++) o[i][r] = 0.f;
    float m_lo = -1e30f, m_hi = -1e30f, l_lo = 0.f, l_hi = 0.f;

    int row_lo = q0 + wrow + grp;
    int row_hi = row_lo + 8;
    int src0 = (lane & ~3) + (tig >> 1);   // quad-shuffle sources for P
    int src1 = src0 + 2;
    bool odd = (tig & 1) != 0;

    for (int kt = 0; kt <= qt; kt++) {
        int c = kt & 1;
        if (kt < qt) {
            // issue K(kt+1) into the other K buffer, then wait for K(kt),V(kt)
            const char* gk = (const char*)(Kp + (size_t)((kt+1)*64 + lrow) * HDIM) + cc0 * 16;
#pragma unroll
            for (int p = 0; p < 16; p++) CP_ASYNC16(kdst[1-c] + p * 16, gk + p * 16);
            CP_COMMIT();
            CP_WAIT1();
        } else {
            CP_WAIT0();
        }
        __syncthreads();

        const float* Ks = kb[c];

        // S = Q @ K^T : warp computes 16x64.
        float s[8][4];
#pragma unroll
        for (int i = 0; i < 8; i++)
#pragma unroll
            for (int r = 0; r < 4; r++) s[i][r] = 0.f;
#pragma unroll
        for (int ks = 0; ks < 16; ks++) {
            int k0 = ks * 8;
#pragma unroll
            for (int ni = 0; ni < 8; ni++) {
                float b0 = Ks[(ni*8 + grp)*SQK + k0 + tig    ];
                float b1 = Ks[(ni*8 + grp)*SQK + k0 + tig + 4];
                mma_tf32(s[ni], qf[ks], b0, b1);
            }
        }
        // apply 1/sqrt(d) once, in fp32
#pragma unroll
        for (int ni = 0; ni < 8; ni++) {
            s[ni][0] *= scale; s[ni][1] *= scale;
            s[ni][2] *= scale; s[ni][3] *= scale;
        }

        // Causal mask (diagonal tile only).
        if (kt == qt) {
            int colbase = kt * 64 + tig * 2;
#pragma unroll
            for (int ni = 0; ni < 8; ni++) {
                int c0 = colbase + ni * 8, c1 = c0 + 1;
                if (c0 > row_lo) s[ni][0] = -1e9f;
                if (c1 > row_lo) s[ni][1] = -1e9f;
                if (c0 > row_hi) s[ni][2] = -1e9f;
                if (c1 > row_hi) s[ni][3] = -1e9f;
            }
        }

        // Online softmax (per row-half; quad lanes share a row).
        float tmax_lo = -1e30f, tmax_hi = -1e30f;
#pragma unroll
        for (int ni = 0; ni < 8; ni++) {
            tmax_lo = fmaxf(tmax_lo, fmaxf(s[ni][0], s[ni][1]));
            tmax_hi = fmaxf(tmax_hi, fmaxf(s[ni][2], s[ni][3]));
        }
#pragma unroll
        for (int o2 = 1; o2 < 4; o2 <<= 1) {
            tmax_lo = fmaxf(tmax_lo, __shfl_xor_sync(0xffffffffu, tmax_lo, o2));
            tmax_hi = fmaxf(tmax_hi, __shfl_xor_sync(0xffffffffu, tmax_hi, o2));
        }
        float mn_lo = fmaxf(m_lo, tmax_lo), mn_hi = fmaxf(m_hi, tmax_hi);
        float al = __expf(m_lo - mn_lo), ah = __expf(m_hi - mn_hi);
        m_lo = mn_lo; m_hi = mn_hi;

        float sum_lo = 0.f, sum_hi = 0.f;
#pragma unroll
        for (int ni = 0; ni < 8; ni++) {
            s[ni][0] = __expf(s[ni][0] - m_lo);
            s[ni][1] = __expf(s[ni][1] - m_lo);
            s[ni][2] = __expf(s[ni][2] - m_hi);
            s[ni][3] = __expf(s[ni][3] - m_hi);
            sum_lo += s[ni][0] + s[ni][1];
            sum_hi += s[ni][2] + s[ni][3];
        }
#pragma unroll
        for (int o2 = 1; o2 < 4; o2 <<= 1) {
            sum_lo += __shfl_xor_sync(0xffffffffu, sum_lo, o2);
            sum_hi += __shfl_xor_sync(0xffffffffu, sum_hi, o2);
        }
        l_lo = l_lo * al + sum_lo;
        l_hi = l_hi * ah + sum_hi;
#pragma unroll
        for (int ni = 0; ni < 16; ni++) {
            o[ni][0] *= al; o[ni][1] *= al;
            o[ni][2] *= ah; o[ni][3] *= ah;
        }

        // O += P @ V : P a-fragments built from s via intra-quad shuffles.
#pragma unroll
        for (int ks2 = 0; ks2 < 8; ks2++) {
            float v00 = __shfl_sync(0xffffffffu, s[ks2][0], src0);
            float v01 = __shfl_sync(0xffffffffu, s[ks2][1], src0);
            float v10 = __shfl_sync(0xffffffffu, s[ks2][2], src0);
            float v11 = __shfl_sync(0xffffffffu, s[ks2][3], src0);
            float v20 = __shfl_sync(0xffffffffu, s[ks2][0], src1);
            float v21 = __shfl_sync(0xffffffffu, s[ks2][1], src1);
            float v30 = __shfl_sync(0xffffffffu, s[ks2][2], src1);
            float v31 = __shfl_sync(0xffffffffu, s[ks2][3], src1);
            float a[4];
            a[0] = to_tf32(odd ? v01 : v00);
            a[1] = to_tf32(odd ? v11 : v10);
            a[2] = to_tf32(odd ? v21 : v20);
            a[3] = to_tf32(odd ? v31 : v30);
            int k0 = ks2 * 8;
#pragma unroll
            for (int ni = 0; ni < 16; ni++) {
                float b0 = Vs[(k0 + tig    )*SV + ni*8 + grp];
                float b1 = Vs[(k0 + tig + 4)*SV + ni*8 + grp];
                mma_tf32(o[ni], a, b0, b1);
            }
        }

        __syncthreads();   // all warps done with Vs (and kb[c])
        if (kt < qt) {
            const char* gv = (const char*)(Vp + (size_t)((kt+1)*64 + lrow) * HDIM) + cc0 * 16;
#pragma unroll
            for (int p = 0; p < 16; p++) CP_ASYNC16(vdst + p * 16, gv + p * 16);
            CP_COMMIT();
        }
    }

    // Epilogue: normalize, write ctx [B,S,E] tf32-rounded (input to O-proj GEMM).
    int b = bh >> 4, h = bh & 15;
    size_t base_lo = ((size_t)b * SEQ + row_lo) * EMBED + h * HDIM;
    size_t base_hi = base_lo + (size_t)8 * EMBED;
    float il_lo = 1.f / l_lo, il_hi = 1.f / l_hi;
#pragma unroll
    for (int ni = 0; ni < 16; ni++) {
        int c = ni * 8 + tig * 2;
        Ctx[base_lo + c]     = to_tf32(o[ni][0] * il_lo);
        Ctx[base_lo + c + 1] = to_tf32(o[ni][1] * il_lo);
        Ctx[base_hi + c]     = to_tf32(o[ni][2] * il_hi);
        Ctx[base_hi + c + 1] = to_tf32(o[ni][3] * il_hi);
    }
}

// ---------------------------------------------------------------------------
extern "C" void kernel_launch(void* const* d_in, const int* in_sizes, int n_in,
                              void* d_out, int out_size) {
    const float* x  = (const float*)d_in[0];
    const float* Wq = (const float*)d_in[1];
    const float* bq = (const float*)d_in[2];
    const float* Wk = (const float*)d_in[3];
    const float* bk = (const float*)d_in[4];
    const float* Wv = (const float*)d_in[5];
    const float* bv = (const float*)d_in[6];
    const float* Wo = (const float*)d_in[7];
    const float* bo = (const float*)d_in[8];
    float* out = (float*)d_out;

    float *Qb, *Kb, *Vb, *Cb, *xr, *Wr;
    cudaGetSymbolAddress((void**)&Qb, g_Q);
    cudaGetSymbolAddress((void**)&Kb, g_K);
    cudaGetSymbolAddress((void**)&Vb, g_V);
    cudaGetSymbolAddress((void**)&Cb, g_C);
    cudaGetSymbolAddress((void**)&xr, g_xr);
    cudaGetSymbolAddress((void**)&Wr, g_Wr);
    float* Wqr = Wr;
    float* Wkr = Wr + (size_t)EMBED * EMBED;
    float* Wvr = Wr + (size_t)2 * EMBED * EMBED;
    float* Wor = Wr + (size_t)3 * EMBED * EMBED;

    const int xn4 = (MROWS * EMBED) / 4;
    const int wn4 = (EMBED * EMBED) / 4;
    round_tf32_kernel<<<xn4 / 256, 256>>>(x,  xr,  xn4);
    round_tf32_kernel<<<wn4 / 256, 256>>>(Wq, Wqr, wn4);
    round_tf32_kernel<<<wn4 / 256, 256>>>(Wk, Wkr, wn4);
    round_tf32_kernel<<<wn4 / 256, 256>>>(Wv, Wvr, wn4);
    round_tf32_kernel<<<wn4 / 256, 256>>>(Wo, Wor, wn4);

    cudaFuncSetAttribute(gemm_tf32_kernel,
                         cudaFuncAttributeMaxDynamicSharedMemorySize, GEMM_SMEM);
    dim3 gg(EMBED / 128, MROWS / 128);  // (16, 32)
    gemm_tf32_kernel<<<gg, 256, GEMM_SMEM>>>(xr, Wqr, bq, Qb, 1);
    gemm_tf32_kernel<<<gg, 256, GEMM_SMEM>>>(xr, Wkr, bk, Kb, 1);
    gemm_tf32_kernel<<<gg, 256, GEMM_SMEM>>>(xr, Wvr, bv, Vb, 1);

    cudaFuncSetAttribute(attn_kernel,
                         cudaFuncAttributeMaxDynamicSharedMemorySize, ATTN_SMEM);
    attn_kernel<<<dim3(SEQ / 64, BATCH * NHEAD), 128, ATTN_SMEM>>>(Qb, Kb, Vb, Cb);

    gemm_tf32_kernel<<<gg, 256, GEMM_SMEM>>>(Cb, Wor, bo, out, 0);
}

// round 7
// speedup vs baseline: 1.3453x; 1.3453x over previous
#include <cuda_runtime.h>
#include <cuda_fp16.h>
#include <cstdint>

#define EMBED 2048
#define NHEAD 16
#define HDIM  128
#define BATCH 2
#define SEQ   2048
#define MROWS (BATCH*SEQ)   // 4096

// Scratch (allocation-free contract: __device__ globals) — float, R4 layouts.
__device__ float g_Q[(size_t)BATCH*NHEAD*SEQ*HDIM];
__device__ float g_K[(size_t)BATCH*NHEAD*SEQ*HDIM];
__device__ float g_V[(size_t)BATCH*NHEAD*SEQ*HDIM];
__device__ float g_C[(size_t)MROWS*EMBED];

__device__ __forceinline__ float to_tf32(float x) {
    uint32_t u;
    asm("cvt.rna.tf32.f32 %0, %1;" : "=r"(u) : "f"(x));
    return __uint_as_float(u);
}

__device__ __forceinline__ void mma_tf32(float c[4], const float a[4], float b0, float b1) {
    asm("mma.sync.aligned.m16n8k8.row.col.f32.tf32.tf32.f32 "
        "{%0,%1,%2,%3}, {%4,%5,%6,%7}, {%8,%9}, {%0,%1,%2,%3};"
        : "+f"(c[0]), "+f"(c[1]), "+f"(c[2]), "+f"(c[3])
        : "r"(__float_as_uint(a[0])), "r"(__float_as_uint(a[1])),
          "r"(__float_as_uint(a[2])), "r"(__float_as_uint(a[3])),
          "r"(__float_as_uint(b0)),  "r"(__float_as_uint(b1)));
}

__device__ __forceinline__ void mma_f16(float c[4], const uint32_t a[4],
                                        uint32_t b0, uint32_t b1) {
    asm("mma.sync.aligned.m16n8k16.row.col.f32.f16.f16.f32 "
        "{%0,%1,%2,%3}, {%4,%5,%6,%7}, {%8,%9}, {%0,%1,%2,%3};"
        : "+f"(c[0]), "+f"(c[1]), "+f"(c[2]), "+f"(c[3])
        : "r"(a[0]), "r"(a[1]), "r"(a[2]), "r"(a[3]), "r"(b0), "r"(b1));
}

__device__ __forceinline__ uint32_t pack2(float lo, float hi) {
    __half2 h = __floats2half2_rn(lo, hi);
    return *(uint32_t*)&h;
}

// ---------------------------------------------------------------------------
// FP16-core GEMM: C[M,N] = A[M,K] @ W[N,K]^T + bias ; fp32 in/out (R4 I/O).
// Block 128x128, K-tile 32 (2 x k16), 8 warps, warp tile 64x32.
// Loads are float4 LDG; fp32->fp16 pack happens at the STS.  Smem stride
// 56 halfs (112 B) -> fragment half2 LDS conflict-free across grp rows.
// mode 0: C row-major fp32 [M,N].  mode 1: fp32 scatter to [B,H,S,D].
// ---------------------------------------------------------------------------
#define GS 56   // smem row stride in halfs

__global__ void __launch_bounds__(256) gemm_f16_kernel(
    const float* __restrict__ A, const float* __restrict__ W,
    const float* __restrict__ bias, float* __restrict__ C, int mode)
{
    __shared__ __align__(16) __half As[128*GS];
    __shared__ __align__(16) __half Bs[128*GS];
    const int K = EMBED;

    int tid  = threadIdx.x;
    int lane = tid & 31, wid = tid >> 5;
    int tig  = lane & 3, grp = lane >> 2;
    int wm   = (wid >> 2) * 64;
    int wn   = (wid & 3) * 32;
    int bm   = blockIdx.y * 128, bn = blockIdx.x * 128;

    const uint32_t* A2 = (const uint32_t*)As;   // half2 view, row stride 28
    const uint32_t* B2 = (const uint32_t*)Bs;

    float acc[4][4][4];
#pragma unroll
    for (int i = 0; i < 4; i++)
#pragma unroll
        for (int j = 0; j < 4; j++)
#pragma unroll
            for (int r = 0; r < 4; r++) acc[i][j][r] = 0.f;

    for (int kt = 0; kt < K; kt += 32) {
        // 128 rows x 32 floats per tile = 1024 float4; pack to half2 pairs.
#pragma unroll
        for (int p = 0; p < 4; p++) {
            int f  = tid + p * 256;
            int r  = f >> 3;
            int c4 = (f & 7) * 4;                       // float (=half) index
            float4 va = *(const float4*)(A + (size_t)(bm + r) * K + kt + c4);
            uint2 ha;
            ha.x = pack2(va.x, va.y);
            ha.y = pack2(va.z, va.w);
            *(uint2*)((char*)As + r * (GS*2) + c4 * 2) = ha;
            float4 vb = *(const float4*)(W + (size_t)(bn + r) * K + kt + c4);
            uint2 hb;
            hb.x = pack2(vb.x, vb.y);
            hb.y = pack2(vb.z, vb.w);
            *(uint2*)((char*)Bs + r * (GS*2) + c4 * 2) = hb;
        }
        __syncthreads();

#pragma unroll
        for (int ks = 0; ks < 2; ks++) {
            int kb = ks * 8 + tig;                      // half2 column index
            uint32_t a[4][4], b[4][2];
#pragma unroll
            for (int mi = 0; mi < 4; mi++) {
                int m0 = wm + mi * 16;
                a[mi][0] = A2[(m0 + grp    ) * 28 + kb    ];
                a[mi][1] = A2[(m0 + grp + 8) * 28 + kb    ];
                a[mi][2] = A2[(m0 + grp    ) * 28 + kb + 4];
                a[mi][3] = A2[(m0 + grp + 8) * 28 + kb + 4];
            }
#pragma unroll
            for (int ni = 0; ni < 4; ni++) {
                int n0 = wn + ni * 8;
                b[ni][0] = B2[(n0 + grp) * 28 + kb    ];
                b[ni][1] = B2[(n0 + grp) * 28 + kb + 4];
            }
#pragma unroll
            for (int mi = 0; mi < 4; mi++)
#pragma unroll
                for (int ni = 0; ni < 4; ni++)
                    mma_f16(acc[mi][ni], a[mi], b[ni][0], b[ni][1]);
        }
        __syncthreads();
    }

    // Epilogue (identical to R4): add bias, write fp32.
#pragma unroll
    for (int mi = 0; mi < 4; mi++) {
#pragma unroll
        for (int ni = 0; ni < 4; ni++) {
            int m0 = bm + wm + mi * 16 + grp;
            int n0 = bn + wn + ni * 8 + tig * 2;
            float bv0 = bias[n0], bv1 = bias[n0 + 1];
            float v00 = acc[mi][ni][0] + bv0, v01 = acc[mi][ni][1] + bv1;
            float v10 = acc[mi][ni][2] + bv0, v11 = acc[mi][ni][3] + bv1;
            if (mode == 0) {
                C[(size_t)m0 * EMBED + n0]       = v00;
                C[(size_t)m0 * EMBED + n0 + 1]   = v01;
                C[(size_t)(m0+8) * EMBED + n0]   = v10;
                C[(size_t)(m0+8) * EMBED + n0+1] = v11;
            } else {
                size_t i0 = ((size_t)((m0 >> 11) * NHEAD + (n0 >> 7))) * (SEQ * HDIM)
                          + (size_t)(m0 & (SEQ-1)) * HDIM + (n0 & (HDIM-1));
                size_t i1 = ((size_t)(((m0+8) >> 11) * NHEAD + (n0 >> 7))) * (SEQ * HDIM)
                          + (size_t)((m0+8) & (SEQ-1)) * HDIM + (n0 & (HDIM-1));
                C[i0] = v00; C[i0 + 1] = v01;
                C[i1] = v10; C[i1 + 1] = v11;
            }
        }
    }
}

// ---------------------------------------------------------------------------
// Causal flash attention — EXACT R4 kernel (passing, 346.6us). Unchanged.
// ---------------------------------------------------------------------------
#define SQK 132
#define SV  136
#define QS_ELEMS (64*SQK)
#define KS_ELEMS (64*SQK)
#define VS_ELEMS (64*SV)
#define ATTN_SMEM ((QS_ELEMS + KS_ELEMS + VS_ELEMS) * 4)   // 102,400 B

__global__ void __launch_bounds__(128, 2) attn_kernel(
    const float* __restrict__ Q, const float* __restrict__ K,
    const float* __restrict__ V, float* __restrict__ Ctx)
{
    extern __shared__ float sm[];
    float* Qs = sm;                // [64][SQK]
    float* Ks = Qs + QS_ELEMS;     // [64][SQK]
    float* Vs = Ks + KS_ELEMS;     // [64][SV]

    int tid  = threadIdx.x;
    int lane = tid & 31, wid = tid >> 5;          // 4 warps
    int tig  = lane & 3, grp = lane >> 2;
    int bh   = blockIdx.y;
    int qt   = gridDim.x - 1 - blockIdx.x;        // big-work blocks first
    int q0   = qt * 64;
    int wrow = wid * 16;

    const size_t off = (size_t)bh * SEQ * HDIM;
    const float* Qp = Q + off + (size_t)q0 * HDIM;
    const float* Kp = K + off;
    const float* Vp = V + off;
    const float scale = 0.08838834764831845f;     // 1/sqrt(128)

    // Load Q tile (64x128 = 2048 float4), pre-scaled + tf32-rounded.
#pragma unroll
    for (int p = 0; p < 16; p++) {
        int f  = tid + p * 128;
        int r  = f >> 5;
        int c4 = (f & 31) << 2;
        float4 v = *(const float4*)(Qp + (size_t)r * HDIM + c4);
        Qs[r*SQK + c4+0] = to_tf32(v.x * scale);
        Qs[r*SQK + c4+1] = to_tf32(v.y * scale);
        Qs[r*SQK + c4+2] = to_tf32(v.z * scale);
        Qs[r*SQK + c4+3] = to_tf32(v.w * scale);
    }
    __syncthreads();

    // Hoist Q fragments for all 16 k-chunks into registers.
    float qf[16][4];
#pragma unroll
    for (int ks = 0; ks < 16; ks++) {
        int k0 = ks * 8;
        qf[ks][0] = Qs[(wrow + grp    )*SQK + k0 + tig    ];
        qf[ks][1] = Qs[(wrow + grp + 8)*SQK + k0 + tig    ];
        qf[ks][2] = Qs[(wrow + grp    )*SQK + k0 + tig + 4];
        qf[ks][3] = Qs[(wrow + grp + 8)*SQK + k0 + tig + 4];
    }

    float o[16][4];
#pragma unroll
    for (int i = 0; i < 16; i++)
#pragma unroll
        for (int r = 0; r < 4; r++) o[i][r] = 0.f;
    float m_lo = -1e30f, m_hi = -1e30f, l_lo = 0.f, l_hi = 0.f;

    int row_lo = q0 + wrow + grp;
    int row_hi = row_lo + 8;
    int src0 = (lane & ~3) + (tig >> 1);   // quad-shuffle sources for P
    int src1 = src0 + 2;
    bool odd = (tig & 1) != 0;

    for (int kt = 0; kt <= qt; kt++) {
        __syncthreads();
        // Load K,V tiles (64x128 = 2048 float4 EACH), tf32-rounded.
#pragma unroll
        for (int p = 0; p < 16; p++) {
            int f  = tid + p * 128;
            int r  = f >> 5;
            int c4 = (f & 31) << 2;
            const float* kp = Kp + (size_t)(kt * 64 + r) * HDIM + c4;
            const float* vp = Vp + (size_t)(kt * 64 + r) * HDIM + c4;
            float4 vk = *(const float4*)kp;
            Ks[r*SQK + c4+0] = to_tf32(vk.x); Ks[r*SQK + c4+1] = to_tf32(vk.y);
            Ks[r*SQK + c4+2] = to_tf32(vk.z); Ks[r*SQK + c4+3] = to_tf32(vk.w);
            float4 vv = *(const float4*)vp;
            Vs[r*SV + c4+0] = to_tf32(vv.x); Vs[r*SV + c4+1] = to_tf32(vv.y);
            Vs[r*SV + c4+2] = to_tf32(vv.z); Vs[r*SV + c4+3] = to_tf32(vv.w);
        }
        __syncthreads();

        // S = Q @ K^T : warp computes 16x64.
        float s[8][4];
#pragma unroll
        for (int i = 0; i < 8; i++)
#pragma unroll
            for (int r = 0; r < 4; r++) s[i][r] = 0.f;
#pragma unroll
        for (int ks = 0; ks < 16; ks++) {
            int k0 = ks * 8;
#pragma unroll
            for (int ni = 0; ni < 8; ni++) {
                float b0 = Ks[(ni*8 + grp)*SQK + k0 + tig    ];
                float b1 = Ks[(ni*8 + grp)*SQK + k0 + tig + 4];
                mma_tf32(s[ni], qf[ks], b0, b1);
            }
        }

        // Causal mask (diagonal tile only; earlier tiles are causally full).
        if (kt == qt) {
            int colbase = kt * 64 + tig * 2;
#pragma unroll
            for (int ni = 0; ni < 8; ni++) {
                int c0 = colbase + ni * 8, c1 = c0 + 1;
                if (c0 > row_lo) s[ni][0] = -1e9f;
                if (c1 > row_lo) s[ni][1] = -1e9f;
                if (c0 > row_hi) s[ni][2] = -1e9f;
                if (c1 > row_hi) s[ni][3] = -1e9f;
            }
        }

        // Online softmax (per row-half; quad lanes share a row).
        float tmax_lo = -1e30f, tmax_hi = -1e30f;
#pragma unroll
        for (int ni = 0; ni < 8; ni++) {
            tmax_lo = fmaxf(tmax_lo, fmaxf(s[ni][0], s[ni][1]));
            tmax_hi = fmaxf(tmax_hi, fmaxf(s[ni][2], s[ni][3]));
        }
#pragma unroll
        for (int o2 = 1; o2 < 4; o2 <<= 1) {
            tmax_lo = fmaxf(tmax_lo, __shfl_xor_sync(0xffffffffu, tmax_lo, o2));
            tmax_hi = fmaxf(tmax_hi, __shfl_xor_sync(0xffffffffu, tmax_hi, o2));
        }
        float mn_lo = fmaxf(m_lo, tmax_lo), mn_hi = fmaxf(m_hi, tmax_hi);
        float al = __expf(m_lo - mn_lo), ah = __expf(m_hi - mn_hi);
        m_lo = mn_lo; m_hi = mn_hi;

        float sum_lo = 0.f, sum_hi = 0.f;
#pragma unroll
        for (int ni = 0; ni < 8; ni++) {
            s[ni][0] = __expf(s[ni][0] - m_lo);
            s[ni][1] = __expf(s[ni][1] - m_lo);
            s[ni][2] = __expf(s[ni][2] - m_hi);
            s[ni][3] = __expf(s[ni][3] - m_hi);
            sum_lo += s[ni][0] + s[ni][1];
            sum_hi += s[ni][2] + s[ni][3];
        }
#pragma unroll
        for (int o2 = 1; o2 < 4; o2 <<= 1) {
            sum_lo += __shfl_xor_sync(0xffffffffu, sum_lo, o2);
            sum_hi += __shfl_xor_sync(0xffffffffu, sum_hi, o2);
        }
        l_lo = l_lo * al + sum_lo;
        l_hi = l_hi * ah + sum_hi;
#pragma unroll
        for (int ni = 0; ni < 16; ni++) {
            o[ni][0] *= al; o[ni][1] *= al;
            o[ni][2] *= ah; o[ni][3] *= ah;
        }

        // O += P @ V. Build P a-fragments from s via intra-quad shuffles.
#pragma unroll
        for (int ks2 = 0; ks2 < 8; ks2++) {
            float v00 = __shfl_sync(0xffffffffu, s[ks2][0], src0);
            float v01 = __shfl_sync(0xffffffffu, s[ks2][1], src0);
            float v10 = __shfl_sync(0xffffffffu, s[ks2][2], src0);
            float v11 = __shfl_sync(0xffffffffu, s[ks2][3], src0);
            float v20 = __shfl_sync(0xffffffffu, s[ks2][0], src1);
            float v21 = __shfl_sync(0xffffffffu, s[ks2][1], src1);
            float v30 = __shfl_sync(0xffffffffu, s[ks2][2], src1);
            float v31 = __shfl_sync(0xffffffffu, s[ks2][3], src1);
            float a[4];
            a[0] = to_tf32(odd ? v01 : v00);
            a[1] = to_tf32(odd ? v11 : v10);
            a[2] = to_tf32(odd ? v21 : v20);
            a[3] = to_tf32(odd ? v31 : v30);
            int k0 = ks2 * 8;
#pragma unroll
            for (int ni = 0; ni < 16; ni++) {
                float b0 = Vs[(k0 + tig    )*SV + ni*8 + grp];
                float b1 = Vs[(k0 + tig + 4)*SV + ni*8 + grp];
                mma_tf32(o[ni], a, b0, b1);
            }
        }
    }

    // Epilogue: normalize, write ctx [B,S,E].
    int b = bh >> 4, h = bh & 15;
    size_t base_lo = ((size_t)b * SEQ + row_lo) * EMBED + h * HDIM;
    size_t base_hi = base_lo + (size_t)8 * EMBED;
    float il_lo = 1.f / l_lo, il_hi = 1.f / l_hi;
#pragma unroll
    for (int ni = 0; ni < 16; ni++) {
        int c = ni * 8 + tig * 2;
        Ctx[base_lo + c]     = o[ni][0] * il_lo;
        Ctx[base_lo + c + 1] = o[ni][1] * il_lo;
        Ctx[base_hi + c]     = o[ni][2] * il_hi;
        Ctx[base_hi + c + 1] = o[ni][3] * il_hi;
    }
}

// ---------------------------------------------------------------------------
extern "C" void kernel_launch(void* const* d_in, const int* in_sizes, int n_in,
                              void* d_out, int out_size) {
    const float* x  = (const float*)d_in[0];
    const float* Wq = (const float*)d_in[1];
    const float* bq = (const float*)d_in[2];
    const float* Wk = (const float*)d_in[3];
    const float* bk = (const float*)d_in[4];
    const float* Wv = (const float*)d_in[5];
    const float* bv = (const float*)d_in[6];
    const float* Wo = (const float*)d_in[7];
    const float* bo = (const float*)d_in[8];
    float* out = (float*)d_out;

    float *Qb, *Kb, *Vb, *Cb;
    cudaGetSymbolAddress((void**)&Qb, g_Q);
    cudaGetSymbolAddress((void**)&Kb, g_K);
    cudaGetSymbolAddress((void**)&Vb, g_V);
    cudaGetSymbolAddress((void**)&Cb, g_C);

    dim3 gg(EMBED / 128, MROWS / 128);  // (16, 32)
    gemm_f16_kernel<<<gg, 256>>>(x, Wq, bq, Qb, 1);
    gemm_f16_kernel<<<gg, 256>>>(x, Wk, bk, Kb, 1);
    gemm_f16_kernel<<<gg, 256>>>(x, Wv, bv, Vb, 1);

    cudaFuncSetAttribute(attn_kernel,
                         cudaFuncAttributeMaxDynamicSharedMemorySize, ATTN_SMEM);
    attn_kernel<<<dim3(SEQ / 64, BATCH * NHEAD), 128, ATTN_SMEM>>>(Qb, Kb, Vb, Cb);

    gemm_f16_kernel<<<gg, 256>>>(Cb, Wo, bo, out, 0);
}

// round 8
// speedup vs baseline: 1.8913x; 1.4058x over previous
#include <cuda_runtime.h>
#include <cuda_fp16.h>
#include <cstdint>

#define EMBED 2048
#define NHEAD 16
#define HDIM  128
#define BATCH 2
#define SEQ   2048
#define MROWS (BATCH*SEQ)   // 4096

// Scratch (allocation-free contract: __device__ globals)
__device__ float  g_Q[(size_t)BATCH*NHEAD*SEQ*HDIM];   // [B,H,S,D] fp32
__device__ float  g_K[(size_t)BATCH*NHEAD*SEQ*HDIM];
__device__ float  g_V[(size_t)BATCH*NHEAD*SEQ*HDIM];
__device__ __half g_C[(size_t)MROWS*EMBED];            // ctx [B,S,E] fp16
__device__ __half g_xh[(size_t)MROWS*EMBED];           // x as fp16
__device__ __half g_Wh[(size_t)4*EMBED*EMBED];         // Wq,Wk,Wv,Wo as fp16

__device__ __forceinline__ float to_tf32(float x) {
    uint32_t u;
    asm("cvt.rna.tf32.f32 %0, %1;" : "=r"(u) : "f"(x));
    return __uint_as_float(u);
}

__device__ __forceinline__ uint32_t smem_u32(const void* p) {
    uint32_t a;
    asm("{ .reg .u64 t; cvta.to.shared.u64 t, %1; cvt.u32.u64 %0, t; }" : "=r"(a) : "l"(p));
    return a;
}

#define CP_ASYNC16(dst, src) \
    asm volatile("cp.async.cg.shared.global [%0], [%1], 16;" :: "r"(dst), "l"(src))
#define CP_COMMIT()  asm volatile("cp.async.commit_group;" ::: "memory")
#define CP_WAIT0()   asm volatile("cp.async.wait_group 0;" ::: "memory")
#define CP_WAIT1()   asm volatile("cp.async.wait_group 1;" ::: "memory")

__device__ __forceinline__ void mma_tf32(float c[4], const float a[4], float b0, float b1) {
    asm("mma.sync.aligned.m16n8k8.row.col.f32.tf32.tf32.f32 "
        "{%0,%1,%2,%3}, {%4,%5,%6,%7}, {%8,%9}, {%0,%1,%2,%3};"
        : "+f"(c[0]), "+f"(c[1]), "+f"(c[2]), "+f"(c[3])
        : "r"(__float_as_uint(a[0])), "r"(__float_as_uint(a[1])),
          "r"(__float_as_uint(a[2])), "r"(__float_as_uint(a[3])),
          "r"(__float_as_uint(b0)),  "r"(__float_as_uint(b1)));
}

__device__ __forceinline__ void mma_f16(float c[4], const uint32_t a[4],
                                        uint32_t b0, uint32_t b1) {
    asm("mma.sync.aligned.m16n8k16.row.col.f32.f16.f16.f32 "
        "{%0,%1,%2,%3}, {%4,%5,%6,%7}, {%8,%9}, {%0,%1,%2,%3};"
        : "+f"(c[0]), "+f"(c[1]), "+f"(c[2]), "+f"(c[3])
        : "r"(a[0]), "r"(a[1]), "r"(a[2]), "r"(a[3]), "r"(b0), "r"(b1));
}

// ===================== fp32 -> fp16 pre-pass =====================
__global__ void f2h_kernel(const float* __restrict__ src,
                           __half* __restrict__ dst, int n4) {
    int i = blockIdx.x * blockDim.x + threadIdx.x;
    if (i < n4) {
        float4 v = ((const float4*)src)[i];
        __half2 a = __floats2half2_rn(v.x, v.y);
        __half2 b = __floats2half2_rn(v.z, v.w);
        uint2 u;
        u.x = *(uint32_t*)&a;
        u.y = *(uint32_t*)&b;
        ((uint2*)dst)[i] = u;
    }
}

// ---------------------------------------------------------------------------
// FP16 GEMM v3: C[M,N] = A[M,K] @ W[N,K]^T + bias ; A, W already fp16.
// Block 128x128, K-tile 32, 8 warps, warp tile 64x32 (R7-proven fragments).
// 3-stage cp.async ring, ONE barrier per K-tile:
//   wait(group t) -> barrier -> issue(t+2) -> mma(t)
// Smem rows 112 B (16B-aligned for cp.async; uint32 stride 28 -> fragment
// LDS conflict-free, verified in R7).
// mode 0: fp32 out row-major [M,N].  mode 1: fp32 scatter to [B,H,S,D].
// ---------------------------------------------------------------------------
#define GPS 112                       // smem row stride, bytes
#define STAGE_B (128*GPS*2)           // A+B per stage = 28,672 B
#define NSTAGE 3
#define GEMM_SMEM (NSTAGE*STAGE_B)    // 86,016 B

__global__ void __launch_bounds__(256) gemm_f16_kernel(
    const __half* __restrict__ A, const __half* __restrict__ W,
    const float* __restrict__ bias, float* __restrict__ C, int mode)
{
    extern __shared__ char gsm[];
    const int K = EMBED;

    int tid  = threadIdx.x;
    int lane = tid & 31, wid = tid >> 5;
    int tig  = lane & 3, grp = lane >> 2;
    int wm   = (wid >> 2) * 64;
    int wn   = (wid & 3) * 32;
    int bm   = blockIdx.y * 128, bn = blockIdx.x * 128;

    // cp.async geometry: thread t -> row r = t>>1, chunks ch0, ch0+1 (16B each;
    // a K-tile row is 32 halfs = 64 B = 4 chunks).
    int r   = tid >> 1;
    int ch0 = (tid & 1) * 2;
    const char* gA = (const char*)(A + (size_t)(bm + r) * K) + ch0 * 16;
    const char* gB = (const char*)(W + (size_t)(bn + r) * K) + ch0 * 16;
    uint32_t sb = smem_u32(gsm);
    uint32_t dA = sb + r * GPS + ch0 * 16;
    uint32_t dB = dA + 128 * GPS;

    float acc[4][4][4];
#pragma unroll
    for (int i = 0; i < 4; i++)
#pragma unroll
        for (int j = 0; j < 4; j++)
#pragma unroll
            for (int q = 0; q < 4; q++) acc[i][j][q] = 0.f;

    // prologue: tiles 0,1 -> stages 0,1
#pragma unroll
    for (int t = 0; t < 2; t++) {
        uint32_t so = t * STAGE_B;
        const char* a = gA + (size_t)t * 64;
        const char* b = gB + (size_t)t * 64;
        CP_ASYNC16(dA + so, a);  CP_ASYNC16(dA + so + 16, a + 16);
        CP_ASYNC16(dB + so, b);  CP_ASYNC16(dB + so + 16, b + 16);
        CP_COMMIT();
    }

    for (int kt = 0; kt < 64; kt++) {
        if (kt < 63) CP_WAIT1(); else CP_WAIT0();   // group kt complete
        __syncthreads();                            // visible to all threads
        if (kt + 2 < 64) {                          // refill stage (kt+2)%3
            int t = kt + 2;
            uint32_t so = (t % NSTAGE) * STAGE_B;
            const char* a = gA + (size_t)t * 64;
            const char* b = gB + (size_t)t * 64;
            CP_ASYNC16(dA + so, a);  CP_ASYNC16(dA + so + 16, a + 16);
            CP_ASYNC16(dB + so, b);  CP_ASYNC16(dB + so + 16, b + 16);
            CP_COMMIT();
        }

        const uint32_t* A2 = (const uint32_t*)(gsm + (kt % NSTAGE) * STAGE_B);
        const uint32_t* B2 = A2 + 128 * (GPS / 4);
#pragma unroll
        for (int ks = 0; ks < 2; ks++) {
            int kb = ks * 8 + tig;                  // half2 column index
            uint32_t a[4][4], b[4][2];
#pragma unroll
            for (int mi = 0; mi < 4; mi++) {
                int m0 = wm + mi * 16;
                a[mi][0] = A2[(m0 + grp    ) * 28 + kb    ];
                a[mi][1] = A2[(m0 + grp + 8) * 28 + kb    ];
                a[mi][2] = A2[(m0 + grp    ) * 28 + kb + 4];
                a[mi][3] = A2[(m0 + grp + 8) * 28 + kb + 4];
            }
#pragma unroll
            for (int ni = 0; ni < 4; ni++) {
                int n0 = wn + ni * 8;
                b[ni][0] = B2[(n0 + grp) * 28 + kb    ];
                b[ni][1] = B2[(n0 + grp) * 28 + kb + 4];
            }
#pragma unroll
            for (int mi = 0; mi < 4; mi++)
#pragma unroll
                for (int ni = 0; ni < 4; ni++)
                    mma_f16(acc[mi][ni], a[mi], b[ni][0], b[ni][1]);
        }
    }

    // Epilogue (R7-identical): add bias, write fp32.
#pragma unroll
    for (int mi = 0; mi < 4; mi++) {
#pragma unroll
        for (int ni = 0; ni < 4; ni++) {
            int m0 = bm + wm + mi * 16 + grp;
            int n0 = bn + wn + ni * 8 + tig * 2;
            float bv0 = bias[n0], bv1 = bias[n0 + 1];
            float v00 = acc[mi][ni][0] + bv0, v01 = acc[mi][ni][1] + bv1;
            float v10 = acc[mi][ni][2] + bv0, v11 = acc[mi][ni][3] + bv1;
            if (mode == 0) {
                C[(size_t)m0 * EMBED + n0]       = v00;
                C[(size_t)m0 * EMBED + n0 + 1]   = v01;
                C[(size_t)(m0+8) * EMBED + n0]   = v10;
                C[(size_t)(m0+8) * EMBED + n0+1] = v11;
            } else {
                size_t i0 = ((size_t)((m0 >> 11) * NHEAD + (n0 >> 7))) * (SEQ * HDIM)
                          + (size_t)(m0 & (SEQ-1)) * HDIM + (n0 & (HDIM-1));
                size_t i1 = ((size_t)(((m0+8) >> 11) * NHEAD + (n0 >> 7))) * (SEQ * HDIM)
                          + (size_t)((m0+8) & (SEQ-1)) * HDIM + (n0 & (HDIM-1));
                C[i0] = v00; C[i0 + 1] = v01;
                C[i1] = v10; C[i1 + 1] = v11;
            }
        }
    }
}

// ---------------------------------------------------------------------------
// Causal flash attention — R4 kernel (passing, 354us), unchanged except the
// epilogue writes ctx as fp16 (same value R7 produced at its STS pack).
// ---------------------------------------------------------------------------
#define SQK 132
#define SV  136
#define QS_ELEMS (64*SQK)
#define KS_ELEMS (64*SQK)
#define VS_ELEMS (64*SV)
#define ATTN_SMEM ((QS_ELEMS + KS_ELEMS + VS_ELEMS) * 4)   // 102,400 B

__global__ void __launch_bounds__(128, 2) attn_kernel(
    const float* __restrict__ Q, const float* __restrict__ K,
    const float* __restrict__ V, __half* __restrict__ Ctx)
{
    extern __shared__ float sm[];
    float* Qs = sm;                // [64][SQK]
    float* Ks = Qs + QS_ELEMS;     // [64][SQK]
    float* Vs = Ks + KS_ELEMS;     // [64][SV]

    int tid  = threadIdx.x;
    int lane = tid & 31, wid = tid >> 5;          // 4 warps
    int tig  = lane & 3, grp = lane >> 2;
    int bh   = blockIdx.y;
    int qt   = gridDim.x - 1 - blockIdx.x;        // big-work blocks first
    int q0   = qt * 64;
    int wrow = wid * 16;

    const size_t off = (size_t)bh * SEQ * HDIM;
    const float* Qp = Q + off + (size_t)q0 * HDIM;
    const float* Kp = K + off;
    const float* Vp = V + off;
    const float scale = 0.08838834764831845f;     // 1/sqrt(128)

#pragma unroll
    for (int p = 0; p < 16; p++) {
        int f  = tid + p * 128;
        int r  = f >> 5;
        int c4 = (f & 31) << 2;
        float4 v = *(const float4*)(Qp + (size_t)r * HDIM + c4);
        Qs[r*SQK + c4+0] = to_tf32(v.x * scale);
        Qs[r*SQK + c4+1] = to_tf32(v.y * scale);
        Qs[r*SQK + c4+2] = to_tf32(v.z * scale);
        Qs[r*SQK + c4+3] = to_tf32(v.w * scale);
    }
    __syncthreads();

    float qf[16][4];
#pragma unroll
    for (int ks = 0; ks < 16; ks++) {
        int k0 = ks * 8;
        qf[ks][0] = Qs[(wrow + grp    )*SQK + k0 + tig    ];
        qf[ks][1] = Qs[(wrow + grp + 8)*SQK + k0 + tig    ];
        qf[ks][2] = Qs[(wrow + grp    )*SQK + k0 + tig + 4];
        qf[ks][3] = Qs[(wrow + grp + 8)*SQK + k0 + tig + 4];
    }

    float o[16][4];
#pragma unroll
    for (int i = 0; i < 16; i++)
#pragma unroll
        for (int r = 0; r < 4; r++) o[i][r] = 0.f;
    float m_lo = -1e30f, m_hi = -1e30f, l_lo = 0.f, l_hi = 0.f;

    int row_lo = q0 + wrow + grp;
    int row_hi = row_lo + 8;
    int src0 = (lane & ~3) + (tig >> 1);
    int src1 = src0 + 2;
    bool odd = (tig & 1) != 0;

    for (int kt = 0; kt <= qt; kt++) {
        __syncthreads();
#pragma unroll
        for (int p = 0; p < 16; p++) {
            int f  = tid + p * 128;
            int r  = f >> 5;
            int c4 = (f & 31) << 2;
            const float* kp = Kp + (size_t)(kt * 64 + r) * HDIM + c4;
            const float* vp = Vp + (size_t)(kt * 64 + r) * HDIM + c4;
            float4 vk = *(const float4*)kp;
            Ks[r*SQK + c4+0] = to_tf32(vk.x); Ks[r*SQK + c4+1] = to_tf32(vk.y);
            Ks[r*SQK + c4+2] = to_tf32(vk.z); Ks[r*SQK + c4+3] = to_tf32(vk.w);
            float4 vv = *(const float4*)vp;
            Vs[r*SV + c4+0] = to_tf32(vv.x); Vs[r*SV + c4+1] = to_tf32(vv.y);
            Vs[r*SV + c4+2] = to_tf32(vv.z); Vs[r*SV + c4+3] = to_tf32(vv.w);
        }
        __syncthreads();

        float s[8][4];
#pragma unroll
        for (int i = 0; i < 8; i++)
#pragma unroll
            for (int r = 0; r < 4; r++) s[i][r] = 0.f;
#pragma unroll
        for (int ks = 0; ks < 16; ks++) {
            int k0 = ks * 8;
#pragma unroll
            for (int ni = 0; ni < 8; ni++) {
                float b0 = Ks[(ni*8 + grp)*SQK + k0 + tig    ];
                float b1 = Ks[(ni*8 + grp)*SQK + k0 + tig + 4];
                mma_tf32(s[ni], qf[ks], b0, b1);
            }
        }

        if (kt == qt) {
            int colbase = kt * 64 + tig * 2;
#pragma unroll
            for (int ni = 0; ni < 8; ni++) {
                int c0 = colbase + ni * 8, c1 = c0 + 1;
                if (c0 > row_lo) s[ni][0] = -1e9f;
                if (c1 > row_lo) s[ni][1] = -1e9f;
                if (c0 > row_hi) s[ni][2] = -1e9f;
                if (c1 > row_hi) s[ni][3] = -1e9f;
            }
        }

        float tmax_lo = -1e30f, tmax_hi = -1e30f;
#pragma unroll
        for (int ni = 0; ni < 8; ni++) {
            tmax_lo = fmaxf(tmax_lo, fmaxf(s[ni][0], s[ni][1]));
            tmax_hi = fmaxf(tmax_hi, fmaxf(s[ni][2], s[ni][3]));
        }
#pragma unroll
        for (int o2 = 1; o2 < 4; o2 <<= 1) {
            tmax_lo = fmaxf(tmax_lo, __shfl_xor_sync(0xffffffffu, tmax_lo, o2));
            tmax_hi = fmaxf(tmax_hi, __shfl_xor_sync(0xffffffffu, tmax_hi, o2));
        }
        float mn_lo = fmaxf(m_lo, tmax_lo), mn_hi = fmaxf(m_hi, tmax_hi);
        float al = __expf(m_lo - mn_lo), ah = __expf(m_hi - mn_hi);
        m_lo = mn_lo; m_hi = mn_hi;

        float sum_lo = 0.f, sum_hi = 0.f;
#pragma unroll
        for (int ni = 0; ni < 8; ni++) {
            s[ni][0] = __expf(s[ni][0] - m_lo);
            s[ni][1] = __expf(s[ni][1] - m_lo);
            s[ni][2] = __expf(s[ni][2] - m_hi);
            s[ni][3] = __expf(s[ni][3] - m_hi);
            sum_lo += s[ni][0] + s[ni][1];
            sum_hi += s[ni][2] + s[ni][3];
        }
#pragma unroll
        for (int o2 = 1; o2 < 4; o2 <<= 1) {
            sum_lo += __shfl_xor_sync(0xffffffffu, sum_lo, o2);
            sum_hi += __shfl_xor_sync(0xffffffffu, sum_hi, o2);
        }
        l_lo = l_lo * al + sum_lo;
        l_hi = l_hi * ah + sum_hi;
#pragma unroll
        for (int ni = 0; ni < 16; ni++) {
            o[ni][0] *= al; o[ni][1] *= al;
            o[ni][2] *= ah; o[ni][3] *= ah;
        }

#pragma unroll
        for (int ks2 = 0; ks2 < 8; ks2++) {
            float v00 = __shfl_sync(0xffffffffu, s[ks2][0], src0);
            float v01 = __shfl_sync(0xffffffffu, s[ks2][1], src0);
            float v10 = __shfl_sync(0xffffffffu, s[ks2][2], src0);
            float v11 = __shfl_sync(0xffffffffu, s[ks2][3], src0);
            float v20 = __shfl_sync(0xffffffffu, s[ks2][0], src1);
            float v21 = __shfl_sync(0xffffffffu, s[ks2][1], src1);
            float v30 = __shfl_sync(0xffffffffu, s[ks2][2], src1);
            float v31 = __shfl_sync(0xffffffffu, s[ks2][3], src1);
            float a[4];
            a[0] = to_tf32(odd ? v01 : v00);
            a[1] = to_tf32(odd ? v11 : v10);
            a[2] = to_tf32(odd ? v21 : v20);
            a[3] = to_tf32(odd ? v31 : v30);
            int k0 = ks2 * 8;
#pragma unroll
            for (int ni = 0; ni < 16; ni++) {
                float b0 = Vs[(k0 + tig    )*SV + ni*8 + grp];
                float b1 = Vs[(k0 + tig + 4)*SV + ni*8 + grp];
                mma_tf32(o[ni], a, b0, b1);
            }
        }
    }

    // Epilogue: normalize, write ctx fp16 [B,S,E].
    int b = bh >> 4, h = bh & 15;
    size_t base_lo = ((size_t)b * SEQ + row_lo) * EMBED + h * HDIM;
    size_t base_hi = base_lo + (size_t)8 * EMBED;
    float il_lo = 1.f / l_lo, il_hi = 1.f / l_hi;
#pragma unroll
    for (int ni = 0; ni < 16; ni++) {
        int c = ni * 8 + tig * 2;
        *(__half2*)(Ctx + base_lo + c) = __floats2half2_rn(o[ni][0]*il_lo, o[ni][1]*il_lo);
        *(__half2*)(Ctx + base_hi + c) = __floats2half2_rn(o[ni][2]*il_hi, o[ni][3]*il_hi);
    }
}

// ---------------------------------------------------------------------------
extern "C" void kernel_launch(void* const* d_in, const int* in_sizes, int n_in,
                              void* d_out, int out_size) {
    const float* x  = (const float*)d_in[0];
    const float* Wq = (const float*)d_in[1];
    const float* bq = (const float*)d_in[2];
    const float* Wk = (const float*)d_in[3];
    const float* bk = (const float*)d_in[4];
    const float* Wv = (const float*)d_in[5];
    const float* bv = (const float*)d_in[6];
    const float* Wo = (const float*)d_in[7];
    const float* bo = (const float*)d_in[8];
    float* out = (float*)d_out;

    float  *Qb, *Kb, *Vb;
    __half *Cb, *xh, *Wh;
    cudaGetSymbolAddress((void**)&Qb, g_Q);
    cudaGetSymbolAddress((void**)&Kb, g_K);
    cudaGetSymbolAddress((void**)&Vb, g_V);
    cudaGetSymbolAddress((void**)&Cb, g_C);
    cudaGetSymbolAddress((void**)&xh, g_xh);
    cudaGetSymbolAddress((void**)&Wh, g_Wh);
    __half* Wqh = Wh;
    __half* Wkh = Wh + (size_t)EMBED * EMBED;
    __half* Wvh = Wh + (size_t)2 * EMBED * EMBED;
    __half* Woh = Wh + (size_t)3 * EMBED * EMBED;

    const int xn4 = (MROWS * EMBED) / 4;   // 2,097,152
    const int wn4 = (EMBED * EMBED) / 4;   // 1,048,576
    f2h_kernel<<<xn4 / 256, 256>>>(x,  xh,  xn4);
    f2h_kernel<<<wn4 / 256, 256>>>(Wq, Wqh, wn4);
    f2h_kernel<<<wn4 / 256, 256>>>(Wk, Wkh, wn4);
    f2h_kernel<<<wn4 / 256, 256>>>(Wv, Wvh, wn4);
    f2h_kernel<<<wn4 / 256, 256>>>(Wo, Woh, wn4);

    cudaFuncSetAttribute(gemm_f16_kernel,
                         cudaFuncAttributeMaxDynamicSharedMemorySize, GEMM_SMEM);
    dim3 gg(EMBED / 128, MROWS / 128);  // (16, 32)
    gemm_f16_kernel<<<gg, 256, GEMM_SMEM>>>(xh, Wqh, bq, Qb, 1);
    gemm_f16_kernel<<<gg, 256, GEMM_SMEM>>>(xh, Wkh, bk, Kb, 1);
    gemm_f16_kernel<<<gg, 256, GEMM_SMEM>>>(xh, Wvh, bv, Vb, 1);

    cudaFuncSetAttribute(attn_kernel,
                         cudaFuncAttributeMaxDynamicSharedMemorySize, ATTN_SMEM);
    attn_kernel<<<dim3(SEQ / 64, BATCH * NHEAD), 128, ATTN_SMEM>>>(Qb, Kb, Vb, Cb);

    gemm_f16_kernel<<<gg, 256, GEMM_SMEM>>>(Cb, Woh, bo, out, 0);
}

// round 9
// speedup vs baseline: 2.3216x; 1.2275x over previous
#include <cuda_runtime.h>
#include <cuda_fp16.h>
#include <cstdint>

#define EMBED 2048
#define NHEAD 16
#define HDIM  128
#define BATCH 2
#define SEQ   2048
#define MROWS (BATCH*SEQ)   // 4096

// Scratch (allocation-free contract: __device__ globals)
__device__ __half g_Q[(size_t)BATCH*NHEAD*SEQ*HDIM];   // [B,H,S,D] fp16
__device__ __half g_K[(size_t)BATCH*NHEAD*SEQ*HDIM];
__device__ __half g_V[(size_t)BATCH*NHEAD*SEQ*HDIM];
__device__ __half g_C[(size_t)MROWS*EMBED];            // ctx [B,S,E] fp16
__device__ __half g_xh[(size_t)MROWS*EMBED];           // x as fp16
__device__ __half g_Wh[(size_t)4*EMBED*EMBED];         // Wq,Wk,Wv,Wo as fp16

__device__ __forceinline__ uint32_t smem_u32(const void* p) {
    uint32_t a;
    asm("{ .reg .u64 t; cvta.to.shared.u64 t, %1; cvt.u32.u64 %0, t; }" : "=r"(a) : "l"(p));
    return a;
}

#define CP_ASYNC16(dst, src) \
    asm volatile("cp.async.cg.shared.global [%0], [%1], 16;" :: "r"(dst), "l"(src))
#define CP_COMMIT()  asm volatile("cp.async.commit_group;" ::: "memory")
#define CP_WAIT0()   asm volatile("cp.async.wait_group 0;" ::: "memory")
#define CP_WAIT1()   asm volatile("cp.async.wait_group 1;" ::: "memory")

__device__ __forceinline__ void mma_f16(float c[4], const uint32_t a[4],
                                        uint32_t b0, uint32_t b1) {
    asm("mma.sync.aligned.m16n8k16.row.col.f32.f16.f16.f32 "
        "{%0,%1,%2,%3}, {%4,%5,%6,%7}, {%8,%9}, {%0,%1,%2,%3};"
        : "+f"(c[0]), "+f"(c[1]), "+f"(c[2]), "+f"(c[3])
        : "r"(a[0]), "r"(a[1]), "r"(a[2]), "r"(a[3]), "r"(b0), "r"(b1));
}

__device__ __forceinline__ uint32_t pack2(float lo, float hi) {
    __half2 h = __floats2half2_rn(lo, hi);
    return *(uint32_t*)&h;
}

// ===================== fp32 -> fp16 pre-pass =====================
__global__ void f2h_kernel(const float* __restrict__ src,
                           __half* __restrict__ dst, int n4) {
    int i = blockIdx.x * blockDim.x + threadIdx.x;
    if (i < n4) {
        float4 v = ((const float4*)src)[i];
        __half2 a = __floats2half2_rn(v.x, v.y);
        __half2 b = __floats2half2_rn(v.z, v.w);
        uint2 u;
        u.x = *(uint32_t*)&a;
        u.y = *(uint32_t*)&b;
        ((uint2*)dst)[i] = u;
    }
}

// ---------------------------------------------------------------------------
// FP16 GEMM v3 (R8-proven): C[M,N] = A[M,K] @ W[N,K]^T + bias; A, W fp16.
// Block 128x128, K-tile 32, 8 warps, 3-stage cp.async ring, 1 barrier/tile.
// mode 0: fp32 out row-major [M,N].  mode 1: HALF out scatter to [B,H,S,D].
// ---------------------------------------------------------------------------
#define GPS 112                       // smem row stride, bytes
#define STAGE_B (128*GPS*2)           // A+B per stage = 28,672 B
#define NSTAGE 3
#define GEMM_SMEM (NSTAGE*STAGE_B)    // 86,016 B

__global__ void __launch_bounds__(256) gemm_f16_kernel(
    const __half* __restrict__ A, const __half* __restrict__ W,
    const float* __restrict__ bias, void* __restrict__ Cv, int mode)
{
    extern __shared__ char gsm[];
    const int K = EMBED;

    int tid  = threadIdx.x;
    int lane = tid & 31, wid = tid >> 5;
    int tig  = lane & 3, grp = lane >> 2;
    int wm   = (wid >> 2) * 64;
    int wn   = (wid & 3) * 32;
    int bm   = blockIdx.y * 128, bn = blockIdx.x * 128;

    int r   = tid >> 1;
    int ch0 = (tid & 1) * 2;
    const char* gA = (const char*)(A + (size_t)(bm + r) * K) + ch0 * 16;
    const char* gB = (const char*)(W + (size_t)(bn + r) * K) + ch0 * 16;
    uint32_t sb = smem_u32(gsm);
    uint32_t dA = sb + r * GPS + ch0 * 16;
    uint32_t dB = dA + 128 * GPS;

    float acc[4][4][4];
#pragma unroll
    for (int i = 0; i < 4; i++)
#pragma unroll
        for (int j = 0; j < 4; j++)
#pragma unroll
            for (int q = 0; q < 4; q++) acc[i][j][q] = 0.f;

#pragma unroll
    for (int t = 0; t < 2; t++) {
        uint32_t so = t * STAGE_B;
        const char* a = gA + (size_t)t * 64;
        const char* b = gB + (size_t)t * 64;
        CP_ASYNC16(dA + so, a);  CP_ASYNC16(dA + so + 16, a + 16);
        CP_ASYNC16(dB + so, b);  CP_ASYNC16(dB + so + 16, b + 16);
        CP_COMMIT();
    }

    for (int kt = 0; kt < 64; kt++) {
        if (kt < 63) CP_WAIT1(); else CP_WAIT0();
        __syncthreads();
        if (kt + 2 < 64) {
            int t = kt + 2;
            uint32_t so = (t % NSTAGE) * STAGE_B;
            const char* a = gA + (size_t)t * 64;
            const char* b = gB + (size_t)t * 64;
            CP_ASYNC16(dA + so, a);  CP_ASYNC16(dA + so + 16, a + 16);
            CP_ASYNC16(dB + so, b);  CP_ASYNC16(dB + so + 16, b + 16);
            CP_COMMIT();
        }

        const uint32_t* A2 = (const uint32_t*)(gsm + (kt % NSTAGE) * STAGE_B);
        const uint32_t* B2 = A2 + 128 * (GPS / 4);
#pragma unroll
        for (int ks = 0; ks < 2; ks++) {
            int kb = ks * 8 + tig;
            uint32_t a[4][4], b[4][2];
#pragma unroll
            for (int mi = 0; mi < 4; mi++) {
                int m0 = wm + mi * 16;
                a[mi][0] = A2[(m0 + grp    ) * 28 + kb    ];
                a[mi][1] = A2[(m0 + grp + 8) * 28 + kb    ];
                a[mi][2] = A2[(m0 + grp    ) * 28 + kb + 4];
                a[mi][3] = A2[(m0 + grp + 8) * 28 + kb + 4];
            }
#pragma unroll
            for (int ni = 0; ni < 4; ni++) {
                int n0 = wn + ni * 8;
                b[ni][0] = B2[(n0 + grp) * 28 + kb    ];
                b[ni][1] = B2[(n0 + grp) * 28 + kb + 4];
            }
#pragma unroll
            for (int mi = 0; mi < 4; mi++)
#pragma unroll
                for (int ni = 0; ni < 4; ni++)
                    mma_f16(acc[mi][ni], a[mi], b[ni][0], b[ni][1]);
        }
    }

#pragma unroll
    for (int mi = 0; mi < 4; mi++) {
#pragma unroll
        for (int ni = 0; ni < 4; ni++) {
            int m0 = bm + wm + mi * 16 + grp;
            int n0 = bn + wn + ni * 8 + tig * 2;
            float bv0 = bias[n0], bv1 = bias[n0 + 1];
            float v00 = acc[mi][ni][0] + bv0, v01 = acc[mi][ni][1] + bv1;
            float v10 = acc[mi][ni][2] + bv0, v11 = acc[mi][ni][3] + bv1;
            if (mode == 0) {
                float* C = (float*)Cv;
                C[(size_t)m0 * EMBED + n0]       = v00;
                C[(size_t)m0 * EMBED + n0 + 1]   = v01;
                C[(size_t)(m0+8) * EMBED + n0]   = v10;
                C[(size_t)(m0+8) * EMBED + n0+1] = v11;
            } else {
                __half* C = (__half*)Cv;
                size_t i0 = ((size_t)((m0 >> 11) * NHEAD + (n0 >> 7))) * (SEQ * HDIM)
                          + (size_t)(m0 & (SEQ-1)) * HDIM + (n0 & (HDIM-1));
                size_t i1 = ((size_t)(((m0+8) >> 11) * NHEAD + (n0 >> 7))) * (SEQ * HDIM)
                          + (size_t)((m0+8) & (SEQ-1)) * HDIM + (n0 & (HDIM-1));
                *(__half2*)(C + i0) = __floats2half2_rn(v00, v01);
                *(__half2*)(C + i1) = __floats2half2_rn(v10, v11);
            }
        }
    }
}

// ---------------------------------------------------------------------------
// Causal flash attention v4 — fp16 mma (m16n8k16).
// 64 q-rows/CTA, 128 threads (4 warps x 16 rows), 64-key tiles.
// - Q/K/V fp16 in [B,H,S,D].  All smem tiles raw uint4 copies (no cvt).
// - Q A-frags & K B-frags: contiguous half2 LDS (row stride 272 B ->
//   conflict-free; verified: (grp*68 + tig) mod 32 unique per lane).
// - PV B-frags: ldmatrix.m8n8.x4.trans on untransposed V tile.
// - P: C-frag -> A-frag is same-lane register pack (R7-convention verified).
// - fp32 softmax & accumulators unchanged from R4/R8.
// ---------------------------------------------------------------------------
#define AS 136   // smem row stride in halfs (272 B = 17 x 16 B)
#define ATTN_SMEM (3*64*AS*2)   // 52,224 B

__global__ void __launch_bounds__(128, 2) attn_kernel(
    const __half* __restrict__ Q, const __half* __restrict__ K,
    const __half* __restrict__ V, __half* __restrict__ Ctx)
{
    extern __shared__ __half hsm[];
    __half* Qs = hsm;              // [64][AS]
    __half* Ks = hsm + 64*AS;      // [64][AS]
    __half* Vs = hsm + 2*64*AS;    // [64][AS]

    int tid  = threadIdx.x;
    int lane = tid & 31, wid = tid >> 5;          // 4 warps
    int tig  = lane & 3, grp = lane >> 2;
    int bh   = blockIdx.y;
    int qt   = gridDim.x - 1 - blockIdx.x;        // big-work blocks first
    int q0   = qt * 64;
    int wrow = wid * 16;

    const size_t off = (size_t)bh * SEQ * HDIM;
    const __half* Qp = Q + off + (size_t)q0 * HDIM;
    const __half* Kp = K + off;
    const __half* Vp = V + off;
    const float scale = 0.08838834764831845f;     // 1/sqrt(128)

    // Load Q tile: 64x128 halfs = 1024 uint4 chunks, 8 per thread.
#pragma unroll
    for (int p = 0; p < 8; p++) {
        int f = tid + p * 128;
        int r = f >> 4, c = (f & 15) * 8;         // half index
        *(uint4*)(Qs + r * AS + c) = *(const uint4*)(Qp + (size_t)r * HDIM + c);
    }
    __syncthreads();

    // Hoist Q A-fragments (8 k16-chunks): contiguous half2 loads.
    uint32_t qf[8][4];
#pragma unroll
    for (int ks = 0; ks < 8; ks++) {
        int kb = ks * 16 + 2 * tig;
        qf[ks][0] = *(const uint32_t*)(Qs + (wrow + grp    ) * AS + kb    );
        qf[ks][1] = *(const uint32_t*)(Qs + (wrow + grp + 8) * AS + kb    );
        qf[ks][2] = *(const uint32_t*)(Qs + (wrow + grp    ) * AS + kb + 8);
        qf[ks][3] = *(const uint32_t*)(Qs + (wrow + grp + 8) * AS + kb + 8);
    }

    float o[16][4];
#pragma unroll
    for (int i = 0; i < 16; i++)
#pragma unroll
        for (int r2 = 0; r2 < 4; r2++) o[i][r2] = 0.f;
    float m_lo = -1e30f, m_hi = -1e30f, l_lo = 0.f, l_hi = 0.f;

    int row_lo = q0 + wrow + grp;
    int row_hi = row_lo + 8;

    // ldmatrix lane geometry (x4: m0 lanes 0-7, m1 8-15, m2 16-23, m3 24-31)
    int lro = (lane & 7) + ((lane >> 3) & 1) * 8;   // row offset within 16
    int lco = (lane >> 4) * 8;                      // col offset 0 or 8
    uint32_t vbase = smem_u32(Vs);

    for (int kt = 0; kt <= qt; kt++) {
        __syncthreads();
        // K,V tiles: 64x128 halfs each, raw copies.
#pragma unroll
        for (int p = 0; p < 8; p++) {
            int f = tid + p * 128;
            int r = f >> 4, c = (f & 15) * 8;
            *(uint4*)(Ks + r * AS + c) =
                *(const uint4*)(Kp + (size_t)(kt * 64 + r) * HDIM + c);
            *(uint4*)(Vs + r * AS + c) =
                *(const uint4*)(Vp + (size_t)(kt * 64 + r) * HDIM + c);
        }
        __syncthreads();

        // S = Q @ K^T : warp computes 16x64 (64 HMMA).
        float s[8][4];
#pragma unroll
        for (int i = 0; i < 8; i++)
#pragma unroll
            for (int r2 = 0; r2 < 4; r2++) s[i][r2] = 0.f;
#pragma unroll
        for (int ks = 0; ks < 8; ks++) {
            int kb = ks * 16 + 2 * tig;
#pragma unroll
            for (int ni = 0; ni < 8; ni++) {
                uint32_t b0 = *(const uint32_t*)(Ks + (ni*8 + grp) * AS + kb    );
                uint32_t b1 = *(const uint32_t*)(Ks + (ni*8 + grp) * AS + kb + 8);
                mma_f16(s[ni], qf[ks], b0, b1);
            }
        }
        // 1/sqrt(d), fp32.
#pragma unroll
        for (int ni = 0; ni < 8; ni++) {
            s[ni][0] *= scale; s[ni][1] *= scale;
            s[ni][2] *= scale; s[ni][3] *= scale;
        }

        // Causal mask (diagonal tile only).
        if (kt == qt) {
            int colbase = kt * 64 + tig * 2;
#pragma unroll
            for (int ni = 0; ni < 8; ni++) {
                int c0 = colbase + ni * 8, c1 = c0 + 1;
                if (c0 > row_lo) s[ni][0] = -1e9f;
                if (c1 > row_lo) s[ni][1] = -1e9f;
                if (c0 > row_hi) s[ni][2] = -1e9f;
                if (c1 > row_hi) s[ni][3] = -1e9f;
            }
        }

        // Online softmax (per row-half; quad lanes share a row).
        float tmax_lo = -1e30f, tmax_hi = -1e30f;
#pragma unroll
        for (int ni = 0; ni < 8; ni++) {
            tmax_lo = fmaxf(tmax_lo, fmaxf(s[ni][0], s[ni][1]));
            tmax_hi = fmaxf(tmax_hi, fmaxf(s[ni][2], s[ni][3]));
        }
#pragma unroll
        for (int o2 = 1; o2 < 4; o2 <<= 1) {
            tmax_lo = fmaxf(tmax_lo, __shfl_xor_sync(0xffffffffu, tmax_lo, o2));
            tmax_hi = fmaxf(tmax_hi, __shfl_xor_sync(0xffffffffu, tmax_hi, o2));
        }
        float mn_lo = fmaxf(m_lo, tmax_lo), mn_hi = fmaxf(m_hi, tmax_hi);
        float al = __expf(m_lo - mn_lo), ah = __expf(m_hi - mn_hi);
        m_lo = mn_lo; m_hi = mn_hi;

        float sum_lo = 0.f, sum_hi = 0.f;
#pragma unroll
        for (int ni = 0; ni < 8; ni++) {
            s[ni][0] = __expf(s[ni][0] - m_lo);
            s[ni][1] = __expf(s[ni][1] - m_lo);
            s[ni][2] = __expf(s[ni][2] - m_hi);
            s[ni][3] = __expf(s[ni][3] - m_hi);
            sum_lo += s[ni][0] + s[ni][1];
            sum_hi += s[ni][2] + s[ni][3];
        }
#pragma unroll
        for (int o2 = 1; o2 < 4; o2 <<= 1) {
            sum_lo += __shfl_xor_sync(0xffffffffu, sum_lo, o2);
            sum_hi += __shfl_xor_sync(0xffffffffu, sum_hi, o2);
        }
        l_lo = l_lo * al + sum_lo;
        l_hi = l_hi * ah + sum_hi;
#pragma unroll
        for (int ni = 0; ni < 16; ni++) {
            o[ni][0] *= al; o[ni][1] *= al;
            o[ni][2] *= ah; o[ni][3] *= ah;
        }

        // O += P @ V.  P: same-lane register pack; V via ldmatrix.trans.
#pragma unroll
        for (int ks2 = 0; ks2 < 4; ks2++) {
            uint32_t a[4];
            a[0] = pack2(s[2*ks2  ][0], s[2*ks2  ][1]);
            a[1] = pack2(s[2*ks2  ][2], s[2*ks2  ][3]);
            a[2] = pack2(s[2*ks2+1][0], s[2*ks2+1][1]);
            a[3] = pack2(s[2*ks2+1][2], s[2*ks2+1][3]);
            uint32_t rowaddr = vbase + (uint32_t)(((ks2*16 + lro) * AS + lco) * 2);
#pragma unroll
            for (int ni2 = 0; ni2 < 8; ni2++) {
                uint32_t b00, b01, b10, b11;
                asm volatile(
                    "ldmatrix.sync.aligned.m8n8.x4.trans.shared.b16 "
                    "{%0,%1,%2,%3}, [%4];"
                    : "=r"(b00), "=r"(b01), "=r"(b10), "=r"(b11)
                    : "r"(rowaddr + (uint32_t)(ni2 * 16 * 2)));
                mma_f16(o[2*ni2    ], a, b00, b01);
                mma_f16(o[2*ni2 + 1], a, b10, b11);
            }
        }
    }

    // Epilogue: normalize, write ctx fp16 [B,S,E].
    int b = bh >> 4, h = bh & 15;
    size_t base_lo = ((size_t)b * SEQ + row_lo) * EMBED + h * HDIM;
    size_t base_hi = base_lo + (size_t)8 * EMBED;
    float il_lo = 1.f / l_lo, il_hi = 1.f / l_hi;
#pragma unroll
    for (int ni = 0; ni < 16; ni++) {
        int c = ni * 8 + tig * 2;
        *(__half2*)(Ctx + base_lo + c) = __floats2half2_rn(o[ni][0]*il_lo, o[ni][1]*il_lo);
        *(__half2*)(Ctx + base_hi + c) = __floats2half2_rn(o[ni][2]*il_hi, o[ni][3]*il_hi);
    }
}

// ---------------------------------------------------------------------------
extern "C" void kernel_launch(void* const* d_in, const int* in_sizes, int n_in,
                              void* d_out, int out_size) {
    const float* x  = (const float*)d_in[0];
    const float* Wq = (const float*)d_in[1];
    const float* bq = (const float*)d_in[2];
    const float* Wk = (const float*)d_in[3];
    const float* bk = (const float*)d_in[4];
    const float* Wv = (const float*)d_in[5];
    const float* bv = (const float*)d_in[6];
    const float* Wo = (const float*)d_in[7];
    const float* bo = (const float*)d_in[8];
    float* out = (float*)d_out;

    __half *Qb, *Kb, *Vb, *Cb, *xh, *Wh;
    cudaGetSymbolAddress((void**)&Qb, g_Q);
    cudaGetSymbolAddress((void**)&Kb, g_K);
    cudaGetSymbolAddress((void**)&Vb, g_V);
    cudaGetSymbolAddress((void**)&Cb, g_C);
    cudaGetSymbolAddress((void**)&xh, g_xh);
    cudaGetSymbolAddress((void**)&Wh, g_Wh);
    __half* Wqh = Wh;
    __half* Wkh = Wh + (size_t)EMBED * EMBED;
    __half* Wvh = Wh + (size_t)2 * EMBED * EMBED;
    __half* Woh = Wh + (size_t)3 * EMBED * EMBED;

    const int xn4 = (MROWS * EMBED) / 4;
    const int wn4 = (EMBED * EMBED) / 4;
    f2h_kernel<<<xn4 / 256, 256>>>(x,  xh,  xn4);
    f2h_kernel<<<wn4 / 256, 256>>>(Wq, Wqh, wn4);
    f2h_kernel<<<wn4 / 256, 256>>>(Wk, Wkh, wn4);
    f2h_kernel<<<wn4 / 256, 256>>>(Wv, Wvh, wn4);
    f2h_kernel<<<wn4 / 256, 256>>>(Wo, Woh, wn4);

    cudaFuncSetAttribute(gemm_f16_kernel,
                         cudaFuncAttributeMaxDynamicSharedMemorySize, GEMM_SMEM);
    dim3 gg(EMBED / 128, MROWS / 128);  // (16, 32)
    gemm_f16_kernel<<<gg, 256, GEMM_SMEM>>>(xh, Wqh, bq, Qb, 1);
    gemm_f16_kernel<<<gg, 256, GEMM_SMEM>>>(xh, Wkh, bk, Kb, 1);
    gemm_f16_kernel<<<gg, 256, GEMM_SMEM>>>(xh, Wvh, bv, Vb, 1);

    cudaFuncSetAttribute(attn_kernel,
                         cudaFuncAttributeMaxDynamicSharedMemorySize, ATTN_SMEM);
    attn_kernel<<<dim3(SEQ / 64, BATCH * NHEAD), 128, ATTN_SMEM>>>(Qb, Kb, Vb, Cb);

    gemm_f16_kernel<<<gg, 256, GEMM_SMEM>>>(Cb, Woh, bo, out, 0);
}

// round 10
// speedup vs baseline: 2.5596x; 1.1025x over previous
#include <cuda_runtime.h>
#include <cuda_fp16.h>
#include <cstdint>

#define EMBED 2048
#define NHEAD 16
#define HDIM  128
#define BATCH 2
#define SEQ   2048
#define MROWS (BATCH*SEQ)   // 4096

// Scratch (allocation-free contract: __device__ globals)
__device__ __half g_Q[(size_t)BATCH*NHEAD*SEQ*HDIM];   // [B,H,S,D] fp16
__device__ __half g_K[(size_t)BATCH*NHEAD*SEQ*HDIM];
__device__ __half g_V[(size_t)BATCH*NHEAD*SEQ*HDIM];
__device__ __half g_C[(size_t)MROWS*EMBED];            // ctx [B,S,E] fp16
__device__ __half g_xh[(size_t)MROWS*EMBED];           // x as fp16
__device__ __half g_Wh[(size_t)4*EMBED*EMBED];         // Wq,Wk,Wv,Wo as fp16

__device__ __forceinline__ uint32_t smem_u32(const void* p) {
    uint32_t a;
    asm("{ .reg .u64 t; cvta.to.shared.u64 t, %1; cvt.u32.u64 %0, t; }" : "=r"(a) : "l"(p));
    return a;
}

#define CP_ASYNC16(dst, src) \
    asm volatile("cp.async.cg.shared.global [%0], [%1], 16;" :: "r"(dst), "l"(src))
#define CP_COMMIT()  asm volatile("cp.async.commit_group;" ::: "memory")
#define CP_WAIT0()   asm volatile("cp.async.wait_group 0;" ::: "memory")
#define CP_WAIT1()   asm volatile("cp.async.wait_group 1;" ::: "memory")

#define LDMATRIX_X4(r0, r1, r2, r3, addr) \
    asm volatile("ldmatrix.sync.aligned.m8n8.x4.shared.b16 {%0,%1,%2,%3}, [%4];" \
                 : "=r"(r0), "=r"(r1), "=r"(r2), "=r"(r3) : "r"(addr))

__device__ __forceinline__ void mma_f16(float c[4], const uint32_t a[4],
                                        uint32_t b0, uint32_t b1) {
    asm("mma.sync.aligned.m16n8k16.row.col.f32.f16.f16.f32 "
        "{%0,%1,%2,%3}, {%4,%5,%6,%7}, {%8,%9}, {%0,%1,%2,%3};"
        : "+f"(c[0]), "+f"(c[1]), "+f"(c[2]), "+f"(c[3])
        : "r"(a[0]), "r"(a[1]), "r"(a[2]), "r"(a[3]), "r"(b0), "r"(b1));
}

__device__ __forceinline__ uint32_t pack2(float lo, float hi) {
    __half2 h = __floats2half2_rn(lo, hi);
    return *(uint32_t*)&h;
}

// ===================== fp32 -> fp16 pre-pass =====================
__global__ void f2h_kernel(const float* __restrict__ src,
                           __half* __restrict__ dst, int n4) {
    int i = blockIdx.x * blockDim.x + threadIdx.x;
    if (i < n4) {
        float4 v = ((const float4*)src)[i];
        __half2 a = __floats2half2_rn(v.x, v.y);
        __half2 b = __floats2half2_rn(v.z, v.w);
        uint2 u;
        u.x = *(uint32_t*)&a;
        u.y = *(uint32_t*)&b;
        ((uint2*)dst)[i] = u;
    }
}

// ---------------------------------------------------------------------------
// FP16 GEMM v4: R8/R9 structure (3-stage cp.async ring, 1 barrier/tile),
// fragment loads via ldmatrix.x4 (12 LDSM/tile/warp instead of 48 LDS.32).
// GPS=112 B rows: 7x16B chunks, 7r mod 8 distinct -> ldmatrix conflict-free.
// mode 0: fp32 out row-major [M,N].  mode 1: HALF out scatter to [B,H,S,D].
// ---------------------------------------------------------------------------
#define GPS 112                       // smem row stride, bytes
#define STAGE_B (128*GPS*2)           // A+B per stage = 28,672 B
#define NSTAGE 3
#define GEMM_SMEM (NSTAGE*STAGE_B)    // 86,016 B

__global__ void __launch_bounds__(256) gemm_f16_kernel(
    const __half* __restrict__ A, const __half* __restrict__ W,
    const float* __restrict__ bias, void* __restrict__ Cv, int mode)
{
    extern __shared__ char gsm[];
    const int K = EMBED;

    int tid  = threadIdx.x;
    int lane = tid & 31, wid = tid >> 5;
    int tig  = lane & 3, grp = lane >> 2;
    int wm   = (wid >> 2) * 64;
    int wn   = (wid & 3) * 32;
    int bm   = blockIdx.y * 128, bn = blockIdx.x * 128;

    int r   = tid >> 1;
    int ch0 = (tid & 1) * 2;
    const char* gA = (const char*)(A + (size_t)(bm + r) * K) + ch0 * 16;
    const char* gB = (const char*)(W + (size_t)(bn + r) * K) + ch0 * 16;
    uint32_t sb = smem_u32(gsm);
    uint32_t dA = sb + r * GPS + ch0 * 16;
    uint32_t dB = dA + 128 * GPS;

    // ldmatrix fragment base addresses (per-lane):
    // A x4: m0=(rows m..m+7,k0) m1=(m+8..15,k0) m2=(m..7,k8) m3=(m+8..15,k8)
    //   lane L -> row (L&7) + ((L>>3)&1)*8, col-16B (L>>4)
    uint32_t aFragB = sb + (uint32_t)(wm + (lane & 7) + ((lane >> 3) & 1) * 8) * GPS
                    + (uint32_t)(lane >> 4) * 16;
    // B x4: m0=(rows n..n+7,k0) m1=(n..7,k8) m2=(n+8..15,k0) m3=(n+8..15,k8)
    //   lane L -> row (L&7) + ((L>>4)&1)*8, col-16B ((L>>3)&1)
    uint32_t bFragB = sb + 128 * GPS
                    + (uint32_t)(wn + (lane & 7) + ((lane >> 4) & 1) * 8) * GPS
                    + (uint32_t)((lane >> 3) & 1) * 16;

    float acc[4][4][4];
#pragma unroll
    for (int i = 0; i < 4; i++)
#pragma unroll
        for (int j = 0; j < 4; j++)
#pragma unroll
            for (int q = 0; q < 4; q++) acc[i][j][q] = 0.f;

#pragma unroll
    for (int t = 0; t < 2; t++) {
        uint32_t so = t * STAGE_B;
        const char* a = gA + (size_t)t * 64;
        const char* b = gB + (size_t)t * 64;
        CP_ASYNC16(dA + so, a);  CP_ASYNC16(dA + so + 16, a + 16);
        CP_ASYNC16(dB + so, b);  CP_ASYNC16(dB + so + 16, b + 16);
        CP_COMMIT();
    }

    for (int kt = 0; kt < 64; kt++) {
        if (kt < 63) CP_WAIT1(); else CP_WAIT0();
        __syncthreads();
        if (kt + 2 < 64) {
            int t = kt + 2;
            uint32_t so = (t % NSTAGE) * STAGE_B;
            const char* a = gA + (size_t)t * 64;
            const char* b = gB + (size_t)t * 64;
            CP_ASYNC16(dA + so, a);  CP_ASYNC16(dA + so + 16, a + 16);
            CP_ASYNC16(dB + so, b);  CP_ASYNC16(dB + so + 16, b + 16);
            CP_COMMIT();
        }

        uint32_t so = (kt % NSTAGE) * STAGE_B;
#pragma unroll
        for (int ks = 0; ks < 2; ks++) {
            uint32_t kso = so + ks * 32;           // k16 chunk = 32 B
            uint32_t a[4][4], b[4][2];
#pragma unroll
            for (int mi = 0; mi < 4; mi++)
                LDMATRIX_X4(a[mi][0], a[mi][1], a[mi][2], a[mi][3],
                            aFragB + kso + (uint32_t)(mi * 16 * GPS));
#pragma unroll
            for (int pr = 0; pr < 2; pr++)
                LDMATRIX_X4(b[2*pr][0], b[2*pr][1], b[2*pr+1][0], b[2*pr+1][1],
                            bFragB + kso + (uint32_t)(pr * 16 * GPS));
#pragma unroll
            for (int mi = 0; mi < 4; mi++)
#pragma unroll
                for (int ni = 0; ni < 4; ni++)
                    mma_f16(acc[mi][ni], a[mi], b[ni][0], b[ni][1]);
        }
    }

#pragma unroll
    for (int mi = 0; mi < 4; mi++) {
#pragma unroll
        for (int ni = 0; ni < 4; ni++) {
            int m0 = bm + wm + mi * 16 + grp;
            int n0 = bn + wn + ni * 8 + tig * 2;
            float bv0 = bias[n0], bv1 = bias[n0 + 1];
            float v00 = acc[mi][ni][0] + bv0, v01 = acc[mi][ni][1] + bv1;
            float v10 = acc[mi][ni][2] + bv0, v11 = acc[mi][ni][3] + bv1;
            if (mode == 0) {
                float* C = (float*)Cv;
                C[(size_t)m0 * EMBED + n0]       = v00;
                C[(size_t)m0 * EMBED + n0 + 1]   = v01;
                C[(size_t)(m0+8) * EMBED + n0]   = v10;
                C[(size_t)(m0+8) * EMBED + n0+1] = v11;
            } else {
                __half* C = (__half*)Cv;
                size_t i0 = ((size_t)((m0 >> 11) * NHEAD + (n0 >> 7))) * (SEQ * HDIM)
                          + (size_t)(m0 & (SEQ-1)) * HDIM + (n0 & (HDIM-1));
                size_t i1 = ((size_t)(((m0+8) >> 11) * NHEAD + (n0 >> 7))) * (SEQ * HDIM)
                          + (size_t)((m0+8) & (SEQ-1)) * HDIM + (n0 & (HDIM-1));
                *(__half2*)(C + i0) = __floats2half2_rn(v00, v01);
                *(__half2*)(C + i1) = __floats2half2_rn(v10, v11);
            }
        }
    }
}

// ---------------------------------------------------------------------------
// Causal flash attention v5 — R9 (proven) + ldmatrix for K B-fragments.
// AS=136 halfs = 272 B = 17x16B rows -> ldmatrix conflict-free.
// ---------------------------------------------------------------------------
#define AS 136
#define ATTN_SMEM (3*64*AS*2)   // 52,224 B

__global__ void __launch_bounds__(128, 2) attn_kernel(
    const __half* __restrict__ Q, const __half* __restrict__ K,
    const __half* __restrict__ V, __half* __restrict__ Ctx)
{
    extern __shared__ __half hsm[];
    __half* Qs = hsm;              // [64][AS]
    __half* Ks = hsm + 64*AS;      // [64][AS]
    __half* Vs = hsm + 2*64*AS;    // [64][AS]

    int tid  = threadIdx.x;
    int lane = tid & 31, wid = tid >> 5;          // 4 warps
    int tig  = lane & 3, grp = lane >> 2;
    int bh   = blockIdx.y;
    int qt   = gridDim.x - 1 - blockIdx.x;        // big-work blocks first
    int q0   = qt * 64;
    int wrow = wid * 16;

    const size_t off = (size_t)bh * SEQ * HDIM;
    const __half* Qp = Q + off + (size_t)q0 * HDIM;
    const __half* Kp = K + off;
    const __half* Vp = V + off;
    const float scale = 0.08838834764831845f;     // 1/sqrt(128)

    // Load Q tile: 64x128 halfs = 1024 uint4 chunks, 8 per thread.
#pragma unroll
    for (int p = 0; p < 8; p++) {
        int f = tid + p * 128;
        int r = f >> 4, c = (f & 15) * 8;
        *(uint4*)(Qs + r * AS + c) = *(const uint4*)(Qp + (size_t)r * HDIM + c);
    }
    __syncthreads();

    // Hoist Q A-fragments (8 k16-chunks).
    uint32_t qf[8][4];
#pragma unroll
    for (int ks = 0; ks < 8; ks++) {
        int kb = ks * 16 + 2 * tig;
        qf[ks][0] = *(const uint32_t*)(Qs + (wrow + grp    ) * AS + kb    );
        qf[ks][1] = *(const uint32_t*)(Qs + (wrow + grp + 8) * AS + kb    );
        qf[ks][2] = *(const uint32_t*)(Qs + (wrow + grp    ) * AS + kb + 8);
        qf[ks][3] = *(const uint32_t*)(Qs + (wrow + grp + 8) * AS + kb + 8);
    }

    float o[16][4];
#pragma unroll
    for (int i = 0; i < 16; i++)
#pragma unroll
        for (int r2 = 0; r2 < 4; r2++) o[i][r2] = 0.f;
    float m_lo = -1e30f, m_hi = -1e30f, l_lo = 0.f, l_hi = 0.f;

    int row_lo = q0 + wrow + grp;
    int row_hi = row_lo + 8;

    // K B-frag ldmatrix base (same lane map as GEMM B):
    uint32_t kFragB = smem_u32(Ks)
                    + (uint32_t)((lane & 7) + ((lane >> 4) & 1) * 8) * (AS*2)
                    + (uint32_t)((lane >> 3) & 1) * 16;

    // V ldmatrix.trans lane geometry (proven in R9).
    int lro = (lane & 7) + ((lane >> 3) & 1) * 8;
    int lco = (lane >> 4) * 8;
    uint32_t vbase = smem_u32(Vs);

    for (int kt = 0; kt <= qt; kt++) {
        __syncthreads();
#pragma unroll
        for (int p = 0; p < 8; p++) {
            int f = tid + p * 128;
            int r = f >> 4, c = (f & 15) * 8;
            *(uint4*)(Ks + r * AS + c) =
                *(const uint4*)(Kp + (size_t)(kt * 64 + r) * HDIM + c);
            *(uint4*)(Vs + r * AS + c) =
                *(const uint4*)(Vp + (size_t)(kt * 64 + r) * HDIM + c);
        }
        __syncthreads();

        // S = Q @ K^T : K fragments via ldmatrix.x4 (4 per ks).
        float s[8][4];
#pragma unroll
        for (int i = 0; i < 8; i++)
#pragma unroll
            for (int r2 = 0; r2 < 4; r2++) s[i][r2] = 0.f;
#pragma unroll
        for (int ks = 0; ks < 8; ks++) {
            uint32_t kso = (uint32_t)(ks * 32);
#pragma unroll
            for (int pr = 0; pr < 4; pr++) {
                uint32_t b00, b01, b10, b11;
                LDMATRIX_X4(b00, b01, b10, b11,
                            kFragB + kso + (uint32_t)(pr * 16 * (AS*2)));
                mma_f16(s[2*pr    ], qf[ks], b00, b01);
                mma_f16(s[2*pr + 1], qf[ks], b10, b11);
            }
        }
#pragma unroll
        for (int ni = 0; ni < 8; ni++) {
            s[ni][0] *= scale; s[ni][1] *= scale;
            s[ni][2] *= scale; s[ni][3] *= scale;
        }

        // Causal mask (diagonal tile only).
        if (kt == qt) {
            int colbase = kt * 64 + tig * 2;
#pragma unroll
            for (int ni = 0; ni < 8; ni++) {
                int c0 = colbase + ni * 8, c1 = c0 + 1;
                if (c0 > row_lo) s[ni][0] = -1e9f;
                if (c1 > row_lo) s[ni][1] = -1e9f;
                if (c0 > row_hi) s[ni][2] = -1e9f;
                if (c1 > row_hi) s[ni][3] = -1e9f;
            }
        }

        // Online softmax.
        float tmax_lo = -1e30f, tmax_hi = -1e30f;
#pragma unroll
        for (int ni = 0; ni < 8; ni++) {
            tmax_lo = fmaxf(tmax_lo, fmaxf(s[ni][0], s[ni][1]));
            tmax_hi = fmaxf(tmax_hi, fmaxf(s[ni][2], s[ni][3]));
        }
#pragma unroll
        for (int o2 = 1; o2 < 4; o2 <<= 1) {
            tmax_lo = fmaxf(tmax_lo, __shfl_xor_sync(0xffffffffu, tmax_lo, o2));
            tmax_hi = fmaxf(tmax_hi, __shfl_xor_sync(0xffffffffu, tmax_hi, o2));
        }
        float mn_lo = fmaxf(m_lo, tmax_lo), mn_hi = fmaxf(m_hi, tmax_hi);
        float al = __expf(m_lo - mn_lo), ah = __expf(m_hi - mn_hi);
        m_lo = mn_lo; m_hi = mn_hi;

        float sum_lo = 0.f, sum_hi = 0.f;
#pragma unroll
        for (int ni = 0; ni < 8; ni++) {
            s[ni][0] = __expf(s[ni][0] - m_lo);
            s[ni][1] = __expf(s[ni][1] - m_lo);
            s[ni][2] = __expf(s[ni][2] - m_hi);
            s[ni][3] = __expf(s[ni][3] - m_hi);
            sum_lo += s[ni][0] + s[ni][1];
            sum_hi += s[ni][2] + s[ni][3];
        }
#pragma unroll
        for (int o2 = 1; o2 < 4; o2 <<= 1) {
            sum_lo += __shfl_xor_sync(0xffffffffu, sum_lo, o2);
            sum_hi += __shfl_xor_sync(0xffffffffu, sum_hi, o2);
        }
        l_lo = l_lo * al + sum_lo;
        l_hi = l_hi * ah + sum_hi;
#pragma unroll
        for (int ni = 0; ni < 16; ni++) {
            o[ni][0] *= al; o[ni][1] *= al;
            o[ni][2] *= ah; o[ni][3] *= ah;
        }

        // O += P @ V (R9-proven: register pack + ldmatrix.trans).
#pragma unroll
        for (int ks2 = 0; ks2 < 4; ks2++) {
            uint32_t a[4];
            a[0] = pack2(s[2*ks2  ][0], s[2*ks2  ][1]);
            a[1] = pack2(s[2*ks2  ][2], s[2*ks2  ][3]);
            a[2] = pack2(s[2*ks2+1][0], s[2*ks2+1][1]);
            a[3] = pack2(s[2*ks2+1][2], s[2*ks2+1][3]);
            uint32_t rowaddr = vbase + (uint32_t)(((ks2*16 + lro) * AS + lco) * 2);
#pragma unroll
            for (int ni2 = 0; ni2 < 8; ni2++) {
                uint32_t b00, b01, b10, b11;
                asm volatile(
                    "ldmatrix.sync.aligned.m8n8.x4.trans.shared.b16 "
                    "{%0,%1,%2,%3}, [%4];"
                    : "=r"(b00), "=r"(b01), "=r"(b10), "=r"(b11)
                    : "r"(rowaddr + (uint32_t)(ni2 * 16 * 2)));
                mma_f16(o[2*ni2    ], a, b00, b01);
                mma_f16(o[2*ni2 + 1], a, b10, b11);
            }
        }
    }

    // Epilogue: normalize, write ctx fp16 [B,S,E].
    int b = bh >> 4, h = bh & 15;
    size_t base_lo = ((size_t)b * SEQ + row_lo) * EMBED + h * HDIM;
    size_t base_hi = base_lo + (size_t)8 * EMBED;
    float il_lo = 1.f / l_lo, il_hi = 1.f / l_hi;
#pragma unroll
    for (int ni = 0; ni < 16; ni++) {
        int c = ni * 8 + tig * 2;
        *(__half2*)(Ctx + base_lo + c) = __floats2half2_rn(o[ni][0]*il_lo, o[ni][1]*il_lo);
        *(__half2*)(Ctx + base_hi + c) = __floats2half2_rn(o[ni][2]*il_hi, o[ni][3]*il_hi);
    }
}

// ---------------------------------------------------------------------------
extern "C" void kernel_launch(void* const* d_in, const int* in_sizes, int n_in,
                              void* d_out, int out_size) {
    const float* x  = (const float*)d_in[0];
    const float* Wq = (const float*)d_in[1];
    const float* bq = (const float*)d_in[2];
    const float* Wk = (const float*)d_in[3];
    const float* bk = (const float*)d_in[4];
    const float* Wv = (const float*)d_in[5];
    const float* bv = (const float*)d_in[6];
    const float* Wo = (const float*)d_in[7];
    const float* bo = (const float*)d_in[8];
    float* out = (float*)d_out;

    __half *Qb, *Kb, *Vb, *Cb, *xh, *Wh;
    cudaGetSymbolAddress((void**)&Qb, g_Q);
    cudaGetSymbolAddress((void**)&Kb, g_K);
    cudaGetSymbolAddress((void**)&Vb, g_V);
    cudaGetSymbolAddress((void**)&Cb, g_C);
    cudaGetSymbolAddress((void**)&xh, g_xh);
    cudaGetSymbolAddress((void**)&Wh, g_Wh);
    __half* Wqh = Wh;
    __half* Wkh = Wh + (size_t)EMBED * EMBED;
    __half* Wvh = Wh + (size_t)2 * EMBED * EMBED;
    __half* Woh = Wh + (size_t)3 * EMBED * EMBED;

    const int xn4 = (MROWS * EMBED) / 4;
    const int wn4 = (EMBED * EMBED) / 4;
    f2h_kernel<<<xn4 / 256, 256>>>(x,  xh,  xn4);
    f2h_kernel<<<wn4 / 256, 256>>>(Wq, Wqh, wn4);
    f2h_kernel<<<wn4 / 256, 256>>>(Wk, Wkh, wn4);
    f2h_kernel<<<wn4 / 256, 256>>>(Wv, Wvh, wn4);
    f2h_kernel<<<wn4 / 256, 256>>>(Wo, Woh, wn4);

    cudaFuncSetAttribute(gemm_f16_kernel,
                         cudaFuncAttributeMaxDynamicSharedMemorySize, GEMM_SMEM);
    dim3 gg(EMBED / 128, MROWS / 128);  // (16, 32)
    gemm_f16_kernel<<<gg, 256, GEMM_SMEM>>>(xh, Wqh, bq, Qb, 1);
    gemm_f16_kernel<<<gg, 256, GEMM_SMEM>>>(xh, Wkh, bk, Kb, 1);
    gemm_f16_kernel<<<gg, 256, GEMM_SMEM>>>(xh, Wvh, bv, Vb, 1);

    cudaFuncSetAttribute(attn_kernel,
                         cudaFuncAttributeMaxDynamicSharedMemorySize, ATTN_SMEM);
    attn_kernel<<<dim3(SEQ / 64, BATCH * NHEAD), 128, ATTN_SMEM>>>(Qb, Kb, Vb, Cb);

    gemm_f16_kernel<<<gg, 256, GEMM_SMEM>>>(Cb, Woh, bo, out, 0);
}